// round 9
// baseline (speedup 1.0000x reference)
#include <cuda_runtime.h>
#include <cuda.h>
#include <cstdint>
#include <cstddef>

#define BQ      8192
#define IN_DIM  1024
#define H_DIM   2048
#define OUT_DIM 1024

#if defined(__CUDA_ARCH_FEAT_SM103_ALL) || defined(__CUDA_ARCH_FEAT_SM100_ALL)
#define TC_OK 1
#else
#define TC_OK 0
#endif

// ---------------- scratch ----------------
__device__ float g_Crr [(size_t)OUT_DIM * H_DIM];   // RNA tf32 Cr
__device__ float g_Cir [(size_t)OUT_DIM * H_DIM];   // RNA tf32 Ci
__device__ float g_BrT [(size_t)IN_DIM * H_DIM];    // Br^T, RNA tf32
__device__ float g_BiTn[(size_t)IN_DIM * H_DIM];    // -Bi^T, RNA tf32
__device__ float g_E   [(size_t)OUT_DIM * IN_DIM];  // Cr@Br - Ci@Bi, RNA tf32
__device__ float g_D   [(size_t)OUT_DIM * H_DIM];   // wr.*Cr - wi.*Ci, RNA tf32

// ---------------- helpers ----------------
__device__ __forceinline__ float rna_tf32(float x) {
    uint32_t r;
    asm("cvt.rna.tf32.f32 %0, %1;" : "=r"(r) : "f"(x));
    return __uint_as_float(r);
}
__device__ __forceinline__ uint32_t smem_u32(const void* p) {
    return (uint32_t)__cvta_generic_to_shared(p);
}
__device__ __forceinline__ void cp16(uint32_t dst, const void* src) {
    asm volatile("cp.async.cg.shared.global [%0], [%1], 16;" :: "r"(dst), "l"(src));
}
__device__ __forceinline__ void cp_commit() { asm volatile("cp.async.commit_group;"); }
template <int N> __device__ __forceinline__ void cp_wait() {
    asm volatile("cp.async.wait_group %0;" :: "n"(N));
}
__device__ __forceinline__ void mbar_init(uint32_t addr, uint32_t cnt) {
    asm volatile("mbarrier.init.shared.b64 [%0], %1;" :: "r"(addr), "r"(cnt) : "memory");
}
__device__ __forceinline__ void mbar_wait(uint32_t addr, uint32_t parity) {
    asm volatile(
        "{\n\t.reg .pred P;\n\t"
        "W%=:\n\t"
        "mbarrier.try_wait.parity.shared::cta.b64 P, [%0], %1, 0x989680;\n\t"
        "@!P bra W%=;\n\t"
        "}" :: "r"(addr), "r"(parity) : "memory");
}
__device__ __forceinline__ void mbar_expect_tx(uint32_t addr, uint32_t bytes) {
    asm volatile("mbarrier.arrive.expect_tx.shared.b64 _, [%0], %1;"
                 :: "r"(addr), "r"(bytes) : "memory");
}
__device__ __forceinline__ void cluster_sync() {
    asm volatile("barrier.cluster.arrive.aligned;" ::: "memory");
    asm volatile("barrier.cluster.wait.aligned;" ::: "memory");
}
__device__ __forceinline__ uint32_t ctarank() {
    uint32_t r;
    asm("mov.u32 %0, %%cluster_ctarank;" : "=r"(r));
    return r;
}
// mma.sync fallback helpers
__device__ __forceinline__ void ldm4(uint32_t& r0, uint32_t& r1, uint32_t& r2, uint32_t& r3, uint32_t a) {
    asm volatile("ldmatrix.sync.aligned.m8n8.x4.shared.b16 {%0,%1,%2,%3}, [%4];"
                 : "=r"(r0), "=r"(r1), "=r"(r2), "=r"(r3) : "r"(a));
}
__device__ __forceinline__ void mma8(float* c, const uint32_t* a, uint32_t b0, uint32_t b1) {
    asm volatile("mma.sync.aligned.m16n8k8.row.col.f32.tf32.tf32.f32 "
                 "{%0,%1,%2,%3}, {%4,%5,%6,%7}, {%8,%9}, {%0,%1,%2,%3};"
                 : "+f"(c[0]), "+f"(c[1]), "+f"(c[2]), "+f"(c[3])
                 : "r"(a[0]), "r"(a[1]), "r"(a[2]), "r"(a[3]), "r"(b0), "r"(b1));
}

#define SST 20
#define STAGE_FLOATS (2 * 128 * SST)

__device__ __forceinline__ void load_tile(float* s, const float* g, int ld) {
#pragma unroll
    for (int c = 0; c < 2; c++) {
        int idx = threadIdx.x + c * 256;
        int row = idx >> 2;
        int kc  = (idx & 3) << 2;
        cp16(smem_u32(s + row * SST + kc), g + (size_t)row * ld + kc);
    }
}
__device__ __forceinline__ void mma_tile(float c[2][8][4], const float* As, const float* Bs,
                                         int wm, int wn, int lane) {
#pragma unroll
    for (int ks = 0; ks < 2; ks++) {
        const int k0 = ks * 8;
        uint32_t af[2][4];
        const int ar = (lane & 7) + ((lane >> 3) & 1) * 8;
        const int ac = k0 + (lane >> 4) * 4;
#pragma unroll
        for (int mi = 0; mi < 2; mi++) {
            uint32_t addr = smem_u32(As + (wm * 32 + mi * 16 + ar) * SST + ac);
            ldm4(af[mi][0], af[mi][1], af[mi][2], af[mi][3], addr);
        }
        const int br = (lane & 7) + ((lane >> 4) ? 8 : 0);
        const int bc = k0 + ((lane >> 3) & 1) * 4;
#pragma unroll
        for (int p = 0; p < 4; p++) {
            uint32_t b0, b1, b2, b3;
            uint32_t addr = smem_u32(Bs + (wn * 64 + p * 16 + br) * SST + bc);
            ldm4(b0, b1, b2, b3, addr);
#pragma unroll
            for (int mi = 0; mi < 2; mi++) {
                mma8(c[mi][2 * p],     af[mi], b0, b1);
                mma8(c[mi][2 * p + 1], af[mi], b2, b3);
            }
        }
    }
}

#if TC_OK
__device__ __forceinline__ void tma2d(uint32_t dst, const CUtensorMap* m, int cx, int cy,
                                      uint32_t mbar) {
    asm volatile(
        "cp.async.bulk.tensor.2d.shared::cta.global.tile.mbarrier::complete_tx::bytes "
        "[%0], [%1, {%2, %3}], [%4];"
        :: "r"(dst), "l"(m), "r"(cx), "r"(cy), "r"(mbar) : "memory");
}
__device__ __forceinline__ void tc_commit(uint32_t mbar) {
    asm volatile("tcgen05.commit.cta_group::1.mbarrier::arrive::one.shared::cluster.b64 [%0];"
                 :: "r"(mbar) : "memory");
}
__device__ __forceinline__ void tc_commit_mc2(uint32_t mbar) {
    asm volatile(
        "tcgen05.commit.cta_group::2.mbarrier::arrive::one.shared::cluster.multicast::cluster.b64 [%0], %1;"
        :: "r"(mbar), "h"((uint16_t)3) : "memory");
}
__device__ __forceinline__ void mma_tf32_ss(uint32_t d_tmem, uint64_t a_desc, uint64_t b_desc,
                                            uint32_t idesc, bool enable) {
    uint32_t en = enable ? 1u : 0u;
    asm volatile(
        "{\n\t.reg .pred p;\n\t"
        "setp.ne.u32 p, %4, 0;\n\t"
        "tcgen05.mma.cta_group::1.kind::tf32 [%0], %1, %2, %3, {%5,%5,%5,%5}, p;\n\t}"
        :: "r"(d_tmem), "l"(a_desc), "l"(b_desc), "r"(idesc), "r"(en), "r"(0u) : "memory");
}
__device__ __forceinline__ void mma_tf32_ss2(uint32_t d_tmem, uint64_t a_desc, uint64_t b_desc,
                                             uint32_t idesc, bool enable) {
    uint32_t en = enable ? 1u : 0u;
    asm volatile(
        "{\n\t.reg .pred p;\n\t"
        "setp.ne.u32 p, %4, 0;\n\t"
        "tcgen05.mma.cta_group::2.kind::tf32 [%0], %1, %2, %3, {%5,%5,%5,%5,%5,%5,%5,%5}, p;\n\t}"
        :: "r"(d_tmem), "l"(a_desc), "l"(b_desc), "r"(idesc), "r"(en), "r"(0u) : "memory");
}
__device__ __forceinline__ uint64_t mk_desc(uint32_t addr) {
    return ((uint64_t)2 << 61) | ((uint64_t)1 << 46) | ((uint64_t)64 << 32) |
           ((uint64_t)1 << 16) | (((uint64_t)addr >> 4) & 0x3FFF);
}
__device__ __forceinline__ void ldtm32(uint32_t* r, uint32_t addr) {
    asm volatile(
        "tcgen05.ld.sync.aligned.32x32b.x32.b32 "
        "{%0,%1,%2,%3,%4,%5,%6,%7,%8,%9,%10,%11,%12,%13,%14,%15,"
        "%16,%17,%18,%19,%20,%21,%22,%23,%24,%25,%26,%27,%28,%29,%30,%31}, [%32];"
        : "=r"(r[0]), "=r"(r[1]), "=r"(r[2]), "=r"(r[3]),
          "=r"(r[4]), "=r"(r[5]), "=r"(r[6]), "=r"(r[7]),
          "=r"(r[8]), "=r"(r[9]), "=r"(r[10]), "=r"(r[11]),
          "=r"(r[12]), "=r"(r[13]), "=r"(r[14]), "=r"(r[15]),
          "=r"(r[16]), "=r"(r[17]), "=r"(r[18]), "=r"(r[19]),
          "=r"(r[20]), "=r"(r[21]), "=r"(r[22]), "=r"(r[23]),
          "=r"(r[24]), "=r"(r[25]), "=r"(r[26]), "=r"(r[27]),
          "=r"(r[28]), "=r"(r[29]), "=r"(r[30]), "=r"(r[31])
        : "r"(addr));
    asm volatile("tcgen05.wait::ld.sync.aligned;" ::: "memory");
}
#endif

// ---------------- merged prep ----------------
__global__ void prep_all(const float* __restrict__ Br, const float* __restrict__ Bi,
                         const float4* __restrict__ Cr4, const float4* __restrict__ Ci4,
                         const float* __restrict__ v_log, const float* __restrict__ theta_log) {
    const int b = blockIdx.x;
    if (b < 4096) {
        __shared__ float tile[32][33];
        const float* src = (b < 2048) ? Br : Bi;
        float* dst = (b < 2048) ? g_BrT : g_BiTn;
        const float sign = (b < 2048) ? 1.0f : -1.0f;
        const int lb = b & 2047;
        const int bx = lb & 31;
        const int by = lb >> 5;
        const int tx = threadIdx.x & 31, ty = threadIdx.x >> 5;
        const int cx = bx * 32 + tx;
        const int ry = by * 32 + ty;
#pragma unroll
        for (int j = 0; j < 32; j += 8)
            tile[ty + j][tx] = src[(size_t)(ry + j) * IN_DIM + cx];
        __syncthreads();
        const int ox = by * 32 + tx;
        const int oy = bx * 32 + ty;
#pragma unroll
        for (int j = 0; j < 32; j += 8)
            dst[(size_t)(oy + j) * H_DIM + ox] = rna_tf32(sign * tile[tx][ty + j]);
    } else {
        int i = (b - 4096) * 256 + threadIdx.x;
        int h0 = (i & (H_DIM / 4 - 1)) * 4;
        float4 cr = Cr4[i], ci = Ci4[i];
        float4 rr, ri;
        rr.x = rna_tf32(cr.x); rr.y = rna_tf32(cr.y);
        rr.z = rna_tf32(cr.z); rr.w = rna_tf32(cr.w);
        ri.x = rna_tf32(ci.x); ri.y = rna_tf32(ci.y);
        ri.z = rna_tf32(ci.z); ri.w = rna_tf32(ci.w);
        ((float4*)g_Crr)[i] = rr;
        ((float4*)g_Cir)[i] = ri;
        float o[4];
        const float* c4r = (const float*)&cr;
        const float* c4i = (const float*)&ci;
#pragma unroll
        for (int k = 0; k < 4; k++) {
            float mag = expf(-expf(v_log[h0 + k]));
            float ang = expf(theta_log[h0 + k]);
            o[k] = rna_tf32(mag * cosf(ang) * c4r[k] - mag * sinf(ang) * c4i[k]);
        }
        ((float4*)g_D)[i] = make_float4(o[0], o[1], o[2], o[3]);
    }
}

// ---------------- cg1 GEMM (fold): out[128*gx, 128*gy] = A @ B^T, TMA producers ----------------
template <int NKT, int KSPLIT, int LDA0, int LDA1, int LDB0, int LDB1, bool ROUND>
__global__ void __launch_bounds__(256, 1) gemm_tc(
    const __grid_constant__ CUtensorMap tmA0, const __grid_constant__ CUtensorMap tmA1,
    const __grid_constant__ CUtensorMap tmB0, const __grid_constant__ CUtensorMap tmB1,
    const float* __restrict__ A0, const float* __restrict__ A1,
    const float* __restrict__ B0, const float* __restrict__ B1,
    float* __restrict__ out, int ldOut)
{
    extern __shared__ __align__(16) char dsm[];
    const int tid = threadIdx.x;
    const int m0 = blockIdx.x * 128;
    const int n0 = blockIdx.y * 128;

#if TC_OK
    constexpr int NS = 4;
    constexpr int TILE16K = 16384;
    constexpr int STAGE = 2 * TILE16K;   // A + B
    const uint32_t sbase = (smem_u32(dsm) + 1023u) & ~1023u;

    __shared__ __align__(8) uint64_t mbar[2 * NS + 1];
    __shared__ uint32_t tmem_slot[1];

    const uint32_t fullA  = smem_u32(&mbar[0]);
    const uint32_t emptyA = smem_u32(&mbar[NS]);
    const uint32_t doneA  = smem_u32(&mbar[2 * NS]);

    if (tid < 32) {
        asm volatile("tcgen05.alloc.cta_group::1.sync.aligned.shared::cta.b32 [%0], %1;"
                     :: "r"(smem_u32(tmem_slot)), "r"(128u) : "memory");
    }
    if (tid == 0) {
#pragma unroll
        for (int s = 0; s < NS; s++) {
            mbar_init(fullA  + 8 * s, 1);
            mbar_init(emptyA + 8 * s, 1);
        }
        mbar_init(doneA, 1);
    }
    __syncthreads();
    const uint32_t tmem = tmem_slot[0];

    if (tid == 0) {
        // single-thread TMA producer
        for (int u = 0; u < NKT; u++) {
            const int s = u & (NS - 1);
            if (u >= NS) mbar_wait(emptyA + 8 * s, ((u / NS) - 1) & 1);
            const int k0 = u * 32;
            mbar_expect_tx(fullA + 8 * s, 2 * TILE16K);
            const uint32_t sa = sbase + s * STAGE;
            if (k0 < KSPLIT) {
                tma2d(sa,           &tmA0, k0, m0, fullA + 8 * s);
                tma2d(sa + TILE16K, &tmB0, k0, n0, fullA + 8 * s);
            } else {
                tma2d(sa,           &tmA1, k0 - KSPLIT, m0, fullA + 8 * s);
                tma2d(sa + TILE16K, &tmB1, k0 - KSPLIT, n0, fullA + 8 * s);
            }
        }
    } else if (tid == 32) {
        // MMA issuer
        asm volatile("tcgen05.fence::after_thread_sync;" ::: "memory");
        const uint32_t idesc = (1u << 4) | (2u << 7) | (2u << 10) |
                               ((128u / 8) << 17) | (8u << 24);
        for (int t = 0; t < NKT; t++) {
            const int s = t & (NS - 1);
            mbar_wait(fullA + 8 * s, (t / NS) & 1);
            const uint64_t ad = mk_desc(sbase + s * STAGE);
            const uint64_t bd = mk_desc(sbase + s * STAGE + TILE16K);
#pragma unroll
            for (int k = 0; k < 4; k++)
                mma_tf32_ss(tmem, ad + 2 * k, bd + 2 * k, idesc, !(t == 0 && k == 0));
            tc_commit(emptyA + 8 * s);
        }
        tc_commit(doneA);
    }

    mbar_wait(doneA, 0);
    asm volatile("tcgen05.fence::after_thread_sync;" ::: "memory");

    if (tid < 128) {
        float* orow = out + (size_t)(m0 + tid) * ldOut + n0;
#pragma unroll
        for (int base = 0; base < 128; base += 32) {
            uint32_t r[32];
            ldtm32(r, tmem + base);
            if (ROUND) {
#pragma unroll
                for (int i = 0; i < 32; i++)
                    r[i] = __float_as_uint(rna_tf32(__uint_as_float(r[i])));
            }
#pragma unroll
            for (int q = 0; q < 8; q++) {
                float4 v;
                v.x = __uint_as_float(r[4 * q + 0]);
                v.y = __uint_as_float(r[4 * q + 1]);
                v.z = __uint_as_float(r[4 * q + 2]);
                v.w = __uint_as_float(r[4 * q + 3]);
                *(float4*)(orow + base + 4 * q) = v;
            }
        }
    }
    asm volatile("tcgen05.fence::before_thread_sync;" ::: "memory");
    __syncthreads();
    if (tid < 32) {
        asm volatile("tcgen05.dealloc.cta_group::1.sync.aligned.b32 %0, %1;"
                     :: "r"(tmem), "r"(128u));
    }
#else
    float* smf = (float*)dsm;
    const int wid = tid >> 5, lane = tid & 31;
    const int wm = wid >> 1, wn = wid & 1;
    const int NKT16 = NKT * 2;
    float c[2][8][4] = {};
#pragma unroll 1
    for (int s = 0; s < 2; s++) {
        int k0 = s * 16;
        const float* Ag = (k0 < KSPLIT) ? A0 + (size_t)m0 * LDA0 + k0
                                        : A1 + (size_t)m0 * LDA1 + (k0 - KSPLIT);
        int lda = (k0 < KSPLIT) ? LDA0 : LDA1;
        const float* Bg = (k0 < KSPLIT) ? B0 + (size_t)n0 * LDB0 + k0
                                        : B1 + (size_t)n0 * LDB1 + (k0 - KSPLIT);
        int ldb = (k0 < KSPLIT) ? LDB0 : LDB1;
        load_tile(smf + s * STAGE_FLOATS, Ag, lda);
        load_tile(smf + s * STAGE_FLOATS + 128 * SST, Bg, ldb);
        cp_commit();
    }
#pragma unroll 1
    for (int t = 0; t < NKT16; t++) {
        if (t + 2 < NKT16) cp_wait<1>(); else cp_wait<0>();
        __syncthreads();
        if (t + 2 < NKT16) {
            int k0 = (t + 2) * 16;
            float* sb = smf + ((t + 2) % 3) * STAGE_FLOATS;
            const float* Ag = (k0 < KSPLIT) ? A0 + (size_t)m0 * LDA0 + k0
                                            : A1 + (size_t)m0 * LDA1 + (k0 - KSPLIT);
            int lda = (k0 < KSPLIT) ? LDA0 : LDA1;
            const float* Bg = (k0 < KSPLIT) ? B0 + (size_t)n0 * LDB0 + k0
                                            : B1 + (size_t)n0 * LDB1 + (k0 - KSPLIT);
            int ldb = (k0 < KSPLIT) ? LDB0 : LDB1;
            load_tile(sb, Ag, lda);
            load_tile(sb + 128 * SST, Bg, ldb);
            cp_commit();
        }
        const float* st = smf + (t % 3) * STAGE_FLOATS;
        mma_tile(c, st, st + 128 * SST, wm, wn, lane);
    }
    __syncthreads();
    const int g = lane >> 2, tq = lane & 3;
#pragma unroll
    for (int mi = 0; mi < 2; mi++)
#pragma unroll
        for (int ni = 0; ni < 8; ni++) {
            int col = n0 + wn * 64 + ni * 8 + 2 * tq;
#pragma unroll
            for (int hf = 0; hf < 2; hf++) {
                int row = m0 + wm * 32 + mi * 16 + hf * 8 + g;
                float2 o;
                o.x = c[mi][ni][hf * 2 + 0];
                o.y = c[mi][ni][hf * 2 + 1];
                if (ROUND) { o.x = rna_tf32(o.x); o.y = rna_tf32(o.y); }
                *(float2*)(out + (size_t)row * ldOut + col) = o;
            }
        }
#endif
}

// ---------------- cg2 main GEMM: pair tile M=256 x N=512, TMA producers ----------------
template <int NKT, int KSPLIT, int LDA0, int LDA1, int LDB0, int LDB1>
__global__ void __launch_bounds__(256, 1) __cluster_dims__(2, 1, 1)
gemm_2cta(const __grid_constant__ CUtensorMap tmA0, const __grid_constant__ CUtensorMap tmA1,
          const __grid_constant__ CUtensorMap tmB0, const __grid_constant__ CUtensorMap tmB1,
          const float* __restrict__ A0, const float* __restrict__ A1,
          const float* __restrict__ B0, const float* __restrict__ B1,
          float* __restrict__ out, int ldOut)
{
    extern __shared__ __align__(16) char dsm[];
    const int tid = threadIdx.x;

#if TC_OK
    constexpr int NS = 4;
    constexpr int TILE16K = 16384;
    constexpr int STAGE = 3 * TILE16K;   // A + Breg0-half + Breg1-half
    const uint32_t sbase = (smem_u32(dsm) + 1023u) & ~1023u;

    __shared__ __align__(8) uint64_t mbar[3 * NS + 1];
    __shared__ uint32_t tmem_slot[1];

    const uint32_t rank = ctarank();
    const int m0 = (blockIdx.x >> 1) * 256 + (int)rank * 128;
    const int n0 = blockIdx.y * 512;

    const uint32_t fullL  = smem_u32(&mbar[0]);        // local TMA completion (tx-based)
    const uint32_t full2  = smem_u32(&mbar[NS]);       // leader: both CTAs ready (2)
    const uint32_t emptyA = smem_u32(&mbar[2 * NS]);   // stage consumed (multicast commit)
    const uint32_t doneA  = smem_u32(&mbar[3 * NS]);

    if (tid < 32) {
        asm volatile("tcgen05.alloc.cta_group::2.sync.aligned.shared::cta.b32 [%0], %1;"
                     :: "r"(smem_u32(tmem_slot)), "r"(512u) : "memory");
    }
    if (tid == 0) {
#pragma unroll
        for (int s = 0; s < NS; s++) {
            mbar_init(fullL  + 8 * s, 1);
            mbar_init(full2  + 8 * s, 2);
            mbar_init(emptyA + 8 * s, 1);
        }
        mbar_init(doneA, 1);
    }
    __syncthreads();
    const uint32_t tmem = tmem_slot[0];
    cluster_sync();   // barriers visible cluster-wide before cross-CTA arrives

    if (tid == 0) {
        // ---------------- single-thread TMA producer ----------------
        for (int u = 0; u < NKT; u++) {
            const int s = u & (NS - 1);
            if (u >= NS) mbar_wait(emptyA + 8 * s, ((u / NS) - 1) & 1);
            const int k0 = u * 32;
            mbar_expect_tx(fullL + 8 * s, 3 * TILE16K);
            const uint32_t sa = sbase + s * STAGE;
            if (k0 < KSPLIT) {
                tma2d(sa,               &tmA0, k0, m0, fullL + 8 * s);
                tma2d(sa + TILE16K,     &tmB0, k0, n0 + 0 * 256 + (int)rank * 128, fullL + 8 * s);
                tma2d(sa + 2 * TILE16K, &tmB0, k0, n0 + 1 * 256 + (int)rank * 128, fullL + 8 * s);
            } else {
                const int kk = k0 - KSPLIT;
                tma2d(sa,               &tmA1, kk, m0, fullL + 8 * s);
                tma2d(sa + TILE16K,     &tmB1, kk, n0 + 0 * 256 + (int)rank * 128, fullL + 8 * s);
                tma2d(sa + 2 * TILE16K, &tmB1, kk, n0 + 1 * 256 + (int)rank * 128, fullL + 8 * s);
            }
        }
    } else if (tid == 32) {
        // ---------------- forwarder: local tiles ready -> leader's full2 ----------------
        for (int t = 0; t < NKT; t++) {
            const int s = t & (NS - 1);
            mbar_wait(fullL + 8 * s, (t / NS) & 1);
            asm volatile(
                "{\n\t.reg .b32 ra;\n\t"
                "mapa.shared::cluster.u32 ra, %0, %1;\n\t"
                "mbarrier.arrive.shared::cluster.b64 _, [ra];\n\t}"
                :: "r"(full2 + 8 * s), "r"(0) : "memory");
        }
    } else if (tid == 64 && rank == 0) {
        // ---------------- MMA issuer (leader) ----------------
        asm volatile("tcgen05.fence::after_thread_sync;" ::: "memory");
        const uint32_t idesc = (1u << 4) | (2u << 7) | (2u << 10) |
                               ((256u / 8) << 17) | ((256u / 16) << 24);
        for (int t = 0; t < NKT; t++) {
            const int s = t & (NS - 1);
            mbar_wait(full2 + 8 * s, (t / NS) & 1);
            const uint64_t ad = mk_desc(sbase + s * STAGE);
#pragma unroll
            for (int r = 0; r < 2; r++) {
                const uint64_t bd = mk_desc(sbase + s * STAGE + TILE16K + r * TILE16K);
#pragma unroll
                for (int k = 0; k < 4; k++)
                    mma_tf32_ss2(tmem + r * 256, ad + 2 * k, bd + 2 * k, idesc,
                                 !(t == 0 && k == 0));
            }
            tc_commit_mc2(emptyA + 8 * s);
        }
        tc_commit_mc2(doneA);
    }

    // ---------------- epilogue: each CTA stores its 128 rows x 512 cols ----------------
    mbar_wait(doneA, 0);
    asm volatile("tcgen05.fence::after_thread_sync;" ::: "memory");

    if (tid < 128) {
        float* orow = out + (size_t)(m0 + tid) * ldOut + n0;
#pragma unroll
        for (int base = 0; base < 512; base += 32) {
            uint32_t r[32];
            ldtm32(r, tmem + base);
#pragma unroll
            for (int q = 0; q < 8; q++) {
                float4 v;
                v.x = __uint_as_float(r[4 * q + 0]);
                v.y = __uint_as_float(r[4 * q + 1]);
                v.z = __uint_as_float(r[4 * q + 2]);
                v.w = __uint_as_float(r[4 * q + 3]);
                *(float4*)(orow + base + 4 * q) = v;
            }
        }
    }
    asm volatile("tcgen05.fence::before_thread_sync;" ::: "memory");
    __syncthreads();
    cluster_sync();
    if (tid < 32) {
        asm volatile("tcgen05.relinquish_alloc_permit.cta_group::2.sync.aligned;");
        asm volatile("tcgen05.dealloc.cta_group::2.sync.aligned.b32 %0, %1;"
                     :: "r"(tmem), "r"(512u));
    }
    cluster_sync();
#else
    // ---------------- fallback: mma.sync ----------------
    float* smf = (float*)dsm;
    const int m0 = blockIdx.x * 128;
    const int n0 = blockIdx.y * 512;
    const int wid = tid >> 5, lane = tid & 31;
    const int wm = wid >> 1, wn = wid & 1;
    const int NKT16 = NKT * 2;

    for (int nh = 0; nh < 4; nh++) {
        const int n0h = n0 + nh * 128;
        float c[2][8][4] = {};
#pragma unroll 1
        for (int s = 0; s < 2; s++) {
            int k0 = s * 16;
            const float* Ag = (k0 < KSPLIT) ? A0 + (size_t)m0 * LDA0 + k0
                                            : A1 + (size_t)m0 * LDA1 + (k0 - KSPLIT);
            int lda = (k0 < KSPLIT) ? LDA0 : LDA1;
            const float* Bg = (k0 < KSPLIT) ? B0 + (size_t)n0h * LDB0 + k0
                                            : B1 + (size_t)n0h * LDB1 + (k0 - KSPLIT);
            int ldb = (k0 < KSPLIT) ? LDB0 : LDB1;
            load_tile(smf + s * STAGE_FLOATS, Ag, lda);
            load_tile(smf + s * STAGE_FLOATS + 128 * SST, Bg, ldb);
            cp_commit();
        }
#pragma unroll 1
        for (int t = 0; t < NKT16; t++) {
            if (t + 2 < NKT16) cp_wait<1>(); else cp_wait<0>();
            __syncthreads();
            if (t + 2 < NKT16) {
                int k0 = (t + 2) * 16;
                float* sb = smf + ((t + 2) % 3) * STAGE_FLOATS;
                const float* Ag = (k0 < KSPLIT) ? A0 + (size_t)m0 * LDA0 + k0
                                                : A1 + (size_t)m0 * LDA1 + (k0 - KSPLIT);
                int lda = (k0 < KSPLIT) ? LDA0 : LDA1;
                const float* Bg = (k0 < KSPLIT) ? B0 + (size_t)n0h * LDB0 + k0
                                                : B1 + (size_t)n0h * LDB1 + (k0 - KSPLIT);
                int ldb = (k0 < KSPLIT) ? LDB0 : LDB1;
                load_tile(sb, Ag, lda);
                load_tile(sb + 128 * SST, Bg, ldb);
                cp_commit();
            }
            const float* st = smf + (t % 3) * STAGE_FLOATS;
            mma_tile(c, st, st + 128 * SST, wm, wn, lane);
        }
        __syncthreads();

        const int g = lane >> 2, tq = lane & 3;
#pragma unroll
        for (int mi = 0; mi < 2; mi++)
#pragma unroll
            for (int ni = 0; ni < 8; ni++) {
                int col = n0h + wn * 64 + ni * 8 + 2 * tq;
#pragma unroll
                for (int hf = 0; hf < 2; hf++) {
                    int row = m0 + wm * 32 + mi * 16 + hf * 8 + g;
                    float2 o;
                    o.x = c[mi][ni][hf * 2 + 0];
                    o.y = c[mi][ni][hf * 2 + 1];
                    *(float2*)(out + (size_t)row * ldOut + col) = o;
                }
            }
    }
#endif
}

// ---------------- host: tensormap encoding via runtime-fetched driver entry ----------------
typedef CUresult (*EncodeFn)(CUtensorMap*, CUtensorMapDataType, cuuint32_t, void*,
                             const cuuint64_t*, const cuuint64_t*, const cuuint32_t*,
                             const cuuint32_t*, CUtensorMapInterleave, CUtensorMapSwizzle,
                             CUtensorMapL2promotion, CUtensorMapFloatOOBfill);

static EncodeFn get_encode_fn() {
    static EncodeFn fn = nullptr;
    if (!fn) {
        cudaDriverEntryPointQueryResult st;
#if CUDART_VERSION >= 12050
        cudaGetDriverEntryPointByVersion("cuTensorMapEncodeTiled", (void**)&fn, 12000,
                                         cudaEnableDefault, &st);
#else
        cudaGetDriverEntryPoint("cuTensorMapEncodeTiled", (void**)&fn, cudaEnableDefault, &st);
#endif
    }
    return fn;
}

static CUtensorMap make_map(const void* p, uint64_t d0, uint64_t d1) {
    CUtensorMap m;
    cuuint64_t dims[2]    = {d0, d1};
    cuuint64_t strides[1] = {d0 * 4};
    cuuint32_t box[2]     = {32, 128};
    cuuint32_t es[2]      = {1, 1};
    get_encode_fn()(&m, CU_TENSOR_MAP_DATA_TYPE_FLOAT32, 2, (void*)p, dims, strides, box, es,
                    CU_TENSOR_MAP_INTERLEAVE_NONE, CU_TENSOR_MAP_SWIZZLE_128B,
                    CU_TENSOR_MAP_L2_PROMOTION_L2_128B, CU_TENSOR_MAP_FLOAT_OOB_FILL_NONE);
    return m;
}

// ---------------- launch ----------------
extern "C" void kernel_launch(void* const* d_in, const int* in_sizes, int n_in,
                              void* d_out, int out_size) {
    const float* x         = (const float*)d_in[0];
    const float* h_prev    = (const float*)d_in[1];
    const float* Br        = (const float*)d_in[2];
    const float* Bi        = (const float*)d_in[3];
    const float* Cr        = (const float*)d_in[4];
    const float* Ci        = (const float*)d_in[5];
    const float* v_log     = (const float*)d_in[6];
    const float* theta_log = (const float*)d_in[7];

    float *p_Crr, *p_Cir, *p_BrT, *p_BiTn, *p_E, *p_D;
    cudaGetSymbolAddress((void**)&p_Crr,  g_Crr);
    cudaGetSymbolAddress((void**)&p_Cir,  g_Cir);
    cudaGetSymbolAddress((void**)&p_BrT,  g_BrT);
    cudaGetSymbolAddress((void**)&p_BiTn, g_BiTn);
    cudaGetSymbolAddress((void**)&p_E,    g_E);
    cudaGetSymbolAddress((void**)&p_D,    g_D);

    // tensormaps ({fastest-dim, rows}, box {32,128}, SW128)
    CUtensorMap tm_Crr  = make_map(p_Crr,  H_DIM,  OUT_DIM);
    CUtensorMap tm_Cir  = make_map(p_Cir,  H_DIM,  OUT_DIM);
    CUtensorMap tm_BrT  = make_map(p_BrT,  H_DIM,  IN_DIM);
    CUtensorMap tm_BiTn = make_map(p_BiTn, H_DIM,  IN_DIM);
    CUtensorMap tm_hp   = make_map(h_prev, H_DIM,  BQ);
    CUtensorMap tm_x    = make_map(x,      IN_DIM, BQ);
    CUtensorMap tm_D    = make_map(p_D,    H_DIM,  OUT_DIM);
    CUtensorMap tm_E    = make_map(p_E,    IN_DIM, OUT_DIM);

    // fold: E = [Cr|Ci] @ [BrT|-BiT]^T   (M=1024, N=1024, K=4096)
    auto* foldK = gemm_tc<128, 2048, 2048, 2048, 2048, 2048, true>;
    // main: out = [hp|x] @ [D|E]^T       (M=8192, N=1024, K=3072; D region first)
    auto* mainK = gemm_2cta<96, 2048, 2048, 1024, 2048, 1024>;

    const int smem_fold = 4 * (2 * 16384) + 1024;   // 132 KB
    const int smem_main = 4 * (3 * 16384) + 1024;   // 197632 B
    cudaFuncSetAttribute(foldK, cudaFuncAttributeMaxDynamicSharedMemorySize, smem_fold);
    cudaFuncSetAttribute(mainK, cudaFuncAttributeMaxDynamicSharedMemorySize, smem_main);

    // launch 0: merged prep (transposes + fused Cr/Ci rounding + D)
    prep_all<<<6144, 256>>>(Br, Bi, (const float4*)Cr, (const float4*)Ci, v_log, theta_log);

    // launch 1: fold GEMM
    foldK<<<dim3(OUT_DIM / 128, IN_DIM / 128), 256, smem_fold>>>(
        tm_Crr, tm_Cir, tm_BrT, tm_BiTn, p_Crr, p_Cir, p_BrT, p_BiTn, p_E, IN_DIM);

    // launch 2: main GEMM — grid (64, 2), cluster (2,1,1)
    mainK<<<dim3(2 * (BQ / 256), OUT_DIM / 512), 256, smem_main>>>(
        tm_hp, tm_x, tm_D, tm_E, h_prev, x, p_D, p_E, (float*)d_out, OUT_DIM);
}

// round 10
// speedup vs baseline: 1.0559x; 1.0559x over previous
#include <cuda_runtime.h>
#include <cstdint>
#include <cstddef>

#define BQ      8192
#define IN_DIM  1024
#define H_DIM   2048
#define OUT_DIM 1024

#if defined(__CUDA_ARCH_FEAT_SM103_ALL) || defined(__CUDA_ARCH_FEAT_SM100_ALL)
#define TC_OK 1
#else
#define TC_OK 0
#endif

// ---------------- scratch ----------------
__device__ float g_Crr [(size_t)OUT_DIM * H_DIM];   // RNA tf32 Cr
__device__ float g_Cir [(size_t)OUT_DIM * H_DIM];   // RNA tf32 Ci
__device__ float g_BrT [(size_t)IN_DIM * H_DIM];    // Br^T, RNA tf32
__device__ float g_BiTn[(size_t)IN_DIM * H_DIM];    // -Bi^T, RNA tf32
__device__ float g_E   [(size_t)OUT_DIM * IN_DIM];  // Cr@Br - Ci@Bi, RNA tf32
__device__ float g_D   [(size_t)OUT_DIM * H_DIM];   // wr.*Cr - wi.*Ci, RNA tf32

// ---------------- helpers ----------------
__device__ __forceinline__ float rna_tf32(float x) {
    uint32_t r;
    asm("cvt.rna.tf32.f32 %0, %1;" : "=r"(r) : "f"(x));
    return __uint_as_float(r);
}
__device__ __forceinline__ uint32_t smem_u32(const void* p) {
    return (uint32_t)__cvta_generic_to_shared(p);
}
__device__ __forceinline__ void cp16(uint32_t dst, const void* src) {
    asm volatile("cp.async.cg.shared.global [%0], [%1], 16;" :: "r"(dst), "l"(src));
}
__device__ __forceinline__ void cp_commit() { asm volatile("cp.async.commit_group;"); }
template <int N> __device__ __forceinline__ void cp_wait() {
    asm volatile("cp.async.wait_group %0;" :: "n"(N));
}
__device__ __forceinline__ uint32_t swz(uint32_t off) {   // SW128
    return off ^ ((off >> 3) & 0x70);
}
__device__ __forceinline__ void mbar_init(uint32_t addr, uint32_t cnt) {
    asm volatile("mbarrier.init.shared.b64 [%0], %1;" :: "r"(addr), "r"(cnt) : "memory");
}
__device__ __forceinline__ void mbar_wait(uint32_t addr, uint32_t parity) {
    asm volatile(
        "{\n\t.reg .pred P;\n\t"
        "W%=:\n\t"
        "mbarrier.try_wait.parity.shared::cta.b64 P, [%0], %1, 0x989680;\n\t"
        "@!P bra W%=;\n\t"
        "}" :: "r"(addr), "r"(parity) : "memory");
}
__device__ __forceinline__ void cp_arrive(uint32_t addr) {
    asm volatile("cp.async.mbarrier.arrive.noinc.shared::cta.b64 [%0];" :: "r"(addr) : "memory");
}
__device__ __forceinline__ void cluster_sync() {
    asm volatile("barrier.cluster.arrive.aligned;" ::: "memory");
    asm volatile("barrier.cluster.wait.aligned;" ::: "memory");
}
__device__ __forceinline__ uint32_t ctarank() {
    uint32_t r;
    asm("mov.u32 %0, %%cluster_ctarank;" : "=r"(r));
    return r;
}
// mma.sync fallback helpers
__device__ __forceinline__ void ldm4(uint32_t& r0, uint32_t& r1, uint32_t& r2, uint32_t& r3, uint32_t a) {
    asm volatile("ldmatrix.sync.aligned.m8n8.x4.shared.b16 {%0,%1,%2,%3}, [%4];"
                 : "=r"(r0), "=r"(r1), "=r"(r2), "=r"(r3) : "r"(a));
}
__device__ __forceinline__ void mma8(float* c, const uint32_t* a, uint32_t b0, uint32_t b1) {
    asm volatile("mma.sync.aligned.m16n8k8.row.col.f32.tf32.tf32.f32 "
                 "{%0,%1,%2,%3}, {%4,%5,%6,%7}, {%8,%9}, {%0,%1,%2,%3};"
                 : "+f"(c[0]), "+f"(c[1]), "+f"(c[2]), "+f"(c[3])
                 : "r"(a[0]), "r"(a[1]), "r"(a[2]), "r"(a[3]), "r"(b0), "r"(b1));
}

#define SST 20
#define STAGE_FLOATS (2 * 128 * SST)

__device__ __forceinline__ void load_tile(float* s, const float* g, int ld) {
#pragma unroll
    for (int c = 0; c < 2; c++) {
        int idx = threadIdx.x + c * 256;
        int row = idx >> 2;
        int kc  = (idx & 3) << 2;
        cp16(smem_u32(s + row * SST + kc), g + (size_t)row * ld + kc);
    }
}
__device__ __forceinline__ void mma_tile(float c[2][8][4], const float* As, const float* Bs,
                                         int wm, int wn, int lane) {
#pragma unroll
    for (int ks = 0; ks < 2; ks++) {
        const int k0 = ks * 8;
        uint32_t af[2][4];
        const int ar = (lane & 7) + ((lane >> 3) & 1) * 8;
        const int ac = k0 + (lane >> 4) * 4;
#pragma unroll
        for (int mi = 0; mi < 2; mi++) {
            uint32_t addr = smem_u32(As + (wm * 32 + mi * 16 + ar) * SST + ac);
            ldm4(af[mi][0], af[mi][1], af[mi][2], af[mi][3], addr);
        }
        const int br = (lane & 7) + ((lane >> 4) ? 8 : 0);
        const int bc = k0 + ((lane >> 3) & 1) * 4;
#pragma unroll
        for (int p = 0; p < 4; p++) {
            uint32_t b0, b1, b2, b3;
            uint32_t addr = smem_u32(Bs + (wn * 64 + p * 16 + br) * SST + bc);
            ldm4(b0, b1, b2, b3, addr);
#pragma unroll
            for (int mi = 0; mi < 2; mi++) {
                mma8(c[mi][2 * p],     af[mi], b0, b1);
                mma8(c[mi][2 * p + 1], af[mi], b2, b3);
            }
        }
    }
}

#if TC_OK
__device__ __forceinline__ void tc_commit(uint32_t mbar) {
    asm volatile("tcgen05.commit.cta_group::1.mbarrier::arrive::one.shared::cluster.b64 [%0];"
                 :: "r"(mbar) : "memory");
}
__device__ __forceinline__ void tc_commit_mc2(uint32_t mbar) {
    asm volatile(
        "tcgen05.commit.cta_group::2.mbarrier::arrive::one.shared::cluster.multicast::cluster.b64 [%0], %1;"
        :: "r"(mbar), "h"((uint16_t)3) : "memory");
}
__device__ __forceinline__ void mma_tf32_ss(uint32_t d_tmem, uint64_t a_desc, uint64_t b_desc,
                                            uint32_t idesc, bool enable) {
    uint32_t en = enable ? 1u : 0u;
    asm volatile(
        "{\n\t.reg .pred p;\n\t"
        "setp.ne.u32 p, %4, 0;\n\t"
        "tcgen05.mma.cta_group::1.kind::tf32 [%0], %1, %2, %3, {%5,%5,%5,%5}, p;\n\t}"
        :: "r"(d_tmem), "l"(a_desc), "l"(b_desc), "r"(idesc), "r"(en), "r"(0u) : "memory");
}
__device__ __forceinline__ void mma_tf32_ss2(uint32_t d_tmem, uint64_t a_desc, uint64_t b_desc,
                                             uint32_t idesc, bool enable) {
    uint32_t en = enable ? 1u : 0u;
    asm volatile(
        "{\n\t.reg .pred p;\n\t"
        "setp.ne.u32 p, %4, 0;\n\t"
        "tcgen05.mma.cta_group::2.kind::tf32 [%0], %1, %2, %3, {%5,%5,%5,%5,%5,%5,%5,%5}, p;\n\t}"
        :: "r"(d_tmem), "l"(a_desc), "l"(b_desc), "r"(idesc), "r"(en), "r"(0u) : "memory");
}
__device__ __forceinline__ uint64_t mk_desc(uint32_t addr) {
    return ((uint64_t)2 << 61) | ((uint64_t)1 << 46) | ((uint64_t)64 << 32) |
           ((uint64_t)1 << 16) | (((uint64_t)addr >> 4) & 0x3FFF);
}
__device__ __forceinline__ void ldtm32(uint32_t* r, uint32_t addr) {
    asm volatile(
        "tcgen05.ld.sync.aligned.32x32b.x32.b32 "
        "{%0,%1,%2,%3,%4,%5,%6,%7,%8,%9,%10,%11,%12,%13,%14,%15,"
        "%16,%17,%18,%19,%20,%21,%22,%23,%24,%25,%26,%27,%28,%29,%30,%31}, [%32];"
        : "=r"(r[0]), "=r"(r[1]), "=r"(r[2]), "=r"(r[3]),
          "=r"(r[4]), "=r"(r[5]), "=r"(r[6]), "=r"(r[7]),
          "=r"(r[8]), "=r"(r[9]), "=r"(r[10]), "=r"(r[11]),
          "=r"(r[12]), "=r"(r[13]), "=r"(r[14]), "=r"(r[15]),
          "=r"(r[16]), "=r"(r[17]), "=r"(r[18]), "=r"(r[19]),
          "=r"(r[20]), "=r"(r[21]), "=r"(r[22]), "=r"(r[23]),
          "=r"(r[24]), "=r"(r[25]), "=r"(r[26]), "=r"(r[27]),
          "=r"(r[28]), "=r"(r[29]), "=r"(r[30]), "=r"(r[31])
        : "r"(addr));
    asm volatile("tcgen05.wait::ld.sync.aligned;" ::: "memory");
}
#endif

// ---------------- merged prep ----------------
// grid 4224 x 256:
//   [0,2048)    BrT  (transpose + RNA)
//   [2048,4096) BiTn (transpose + negate + RNA)
//   [4096,4224) fused rounding + D: thread owns 4 h-values (w computed ONCE),
//               loops 16 out-rows: writes Crr, Cir, D.
__global__ void prep_all(const float* __restrict__ Br, const float* __restrict__ Bi,
                         const float4* __restrict__ Cr4, const float4* __restrict__ Ci4,
                         const float* __restrict__ v_log, const float* __restrict__ theta_log) {
    const int b = blockIdx.x;
    if (b < 4096) {
        __shared__ float tile[32][33];
        const float* src = (b < 2048) ? Br : Bi;
        float* dst = (b < 2048) ? g_BrT : g_BiTn;
        const float sign = (b < 2048) ? 1.0f : -1.0f;
        const int lb = b & 2047;
        const int bx = lb & 31;
        const int by = lb >> 5;
        const int tx = threadIdx.x & 31, ty = threadIdx.x >> 5;
        const int cx = bx * 32 + tx;
        const int ry = by * 32 + ty;
#pragma unroll
        for (int j = 0; j < 32; j += 8)
            tile[ty + j][tx] = src[(size_t)(ry + j) * IN_DIM + cx];
        __syncthreads();
        const int ox = by * 32 + tx;
        const int oy = bx * 32 + ty;
#pragma unroll
        for (int j = 0; j < 32; j += 8)
            dst[(size_t)(oy + j) * H_DIM + ox] = rna_tf32(sign * tile[tx][ty + j]);
    } else {
        const int b2 = b - 4096;             // 0..127
        const int og = b2 >> 1;              // out-row group (0..63), 16 rows each
        const int hh = b2 & 1;               // h-half
        const int j4 = hh * 256 + threadIdx.x;   // float4 index into H/4=512
        const int h0 = j4 * 4;

        // w computed once per thread (4 h-values)
        float wr[4], wi[4];
#pragma unroll
        for (int k = 0; k < 4; k++) {
            float mag = expf(-expf(v_log[h0 + k]));
            float ang = expf(theta_log[h0 + k]);
            wr[k] = mag * cosf(ang);
            wi[k] = mag * sinf(ang);
        }
#pragma unroll 1
        for (int r = 0; r < 16; r++) {
            int row = og * 16 + r;
            size_t i = (size_t)row * (H_DIM / 4) + j4;
            float4 cr = Cr4[i], ci = Ci4[i];
            float4 rr, ri;
            rr.x = rna_tf32(cr.x); rr.y = rna_tf32(cr.y);
            rr.z = rna_tf32(cr.z); rr.w = rna_tf32(cr.w);
            ri.x = rna_tf32(ci.x); ri.y = rna_tf32(ci.y);
            ri.z = rna_tf32(ci.z); ri.w = rna_tf32(ci.w);
            ((float4*)g_Crr)[i] = rr;
            ((float4*)g_Cir)[i] = ri;
            const float* c4r = (const float*)&cr;
            const float* c4i = (const float*)&ci;
            float o[4];
#pragma unroll
            for (int k = 0; k < 4; k++)
                o[k] = rna_tf32(wr[k] * c4r[k] - wi[k] * c4i[k]);
            ((float4*)g_D)[i] = make_float4(o[0], o[1], o[2], o[3]);
        }
    }
}

// ---------------- cg1 GEMM (fold): out[128*gx, NTILE*gy] = A @ B^T ----------------
template <int NTILE, int NKT, int KSPLIT, int LDA0, int LDA1, int LDB0, int LDB1, bool ROUND>
__global__ void __launch_bounds__(256, 1) gemm_tc(
    const float* __restrict__ A0, const float* __restrict__ A1,
    const float* __restrict__ B0, const float* __restrict__ B1,
    float* __restrict__ out, int ldOut)
{
    extern __shared__ __align__(16) char dsm[];
    const int tid = threadIdx.x;
    const int m0 = blockIdx.x * 128;
    const int n0 = blockIdx.y * NTILE;

#if TC_OK
    constexpr int NS = 4;
    constexpr int ABYTES = 128 * 128;
    constexpr int STAGE  = ABYTES + NTILE * 128;
    const uint32_t sbase = (smem_u32(dsm) + 1023u) & ~1023u;

    __shared__ __align__(8) uint64_t mbar[2 * NS + 1];
    __shared__ uint32_t tmem_slot[1];

    const uint32_t fullA  = smem_u32(&mbar[0]);
    const uint32_t emptyA = smem_u32(&mbar[NS]);
    const uint32_t doneA  = smem_u32(&mbar[2 * NS]);

    if (tid < 32) {
        asm volatile("tcgen05.alloc.cta_group::1.sync.aligned.shared::cta.b32 [%0], %1;"
                     :: "r"(smem_u32(tmem_slot)), "r"((uint32_t)NTILE) : "memory");
    }
    if (tid == 0) {
#pragma unroll
        for (int s = 0; s < NS; s++) {
            mbar_init(fullA  + 8 * s, 128);
            mbar_init(emptyA + 8 * s, 1);
        }
        mbar_init(doneA, 1);
    }
    __syncthreads();
    const uint32_t tmem = tmem_slot[0];

    if (tid < 128) {
        for (int u = 0; u < NKT; u++) {
            const int s = u & (NS - 1);
            if (u >= NS) mbar_wait(emptyA + 8 * s, ((u / NS) - 1) & 1);
            const int k0 = u * 32;
            const float* Ag; int lda;
            const float* Bg; int ldb;
            if (k0 < KSPLIT) { Ag = A0 + (size_t)m0 * LDA0 + k0; lda = LDA0; }
            else             { Ag = A1 + (size_t)m0 * LDA1 + (k0 - KSPLIT); lda = LDA1; }
            if (k0 < KSPLIT) { Bg = B0 + (size_t)n0 * LDB0 + k0; ldb = LDB0; }
            else             { Bg = B1 + (size_t)n0 * LDB1 + (k0 - KSPLIT); ldb = LDB1; }
            const uint32_t sa = sbase + s * STAGE;
            const uint32_t sb = sa + ABYTES;
#pragma unroll
            for (int c = 0; c < 8; c++) {
                int i = tid + c * 128;
                int row = i >> 3, kc = i & 7;
                cp16(sa + swz(row * 128 + kc * 16), Ag + (size_t)row * lda + kc * 4);
            }
#pragma unroll
            for (int c = 0; c < NTILE / 16; c++) {
                int i = tid + c * 128;
                int row = i >> 3, kc = i & 7;
                cp16(sb + swz(row * 128 + kc * 16), Bg + (size_t)row * ldb + kc * 4);
            }
            cp_arrive(fullA + 8 * s);
        }
    } else if (tid == 128) {
        asm volatile("tcgen05.fence::after_thread_sync;" ::: "memory");
        const uint32_t idesc = (1u << 4) | (2u << 7) | (2u << 10) |
                               ((uint32_t)(NTILE / 8) << 17) | (8u << 24);
        for (int t = 0; t < NKT; t++) {
            const int s = t & (NS - 1);
            mbar_wait(fullA + 8 * s, (t / NS) & 1);
            asm volatile("fence.proxy.async.shared::cta;" ::: "memory");
            const uint64_t ad = mk_desc(sbase + s * STAGE);
            const uint64_t bd = mk_desc(sbase + s * STAGE + ABYTES);
#pragma unroll
            for (int k = 0; k < 4; k++)
                mma_tf32_ss(tmem, ad + 2 * k, bd + 2 * k, idesc, !(t == 0 && k == 0));
            tc_commit(emptyA + 8 * s);
        }
        tc_commit(doneA);
    }

    mbar_wait(doneA, 0);
    asm volatile("tcgen05.fence::after_thread_sync;" ::: "memory");

    if (tid < 128) {
        float* orow = out + (size_t)(m0 + tid) * ldOut + n0;
#pragma unroll
        for (int base = 0; base < NTILE; base += 32) {
            uint32_t r[32];
            ldtm32(r, tmem + base);
            if (ROUND) {
#pragma unroll
                for (int i = 0; i < 32; i++)
                    r[i] = __float_as_uint(rna_tf32(__uint_as_float(r[i])));
            }
#pragma unroll
            for (int q = 0; q < 8; q++) {
                float4 v;
                v.x = __uint_as_float(r[4 * q + 0]);
                v.y = __uint_as_float(r[4 * q + 1]);
                v.z = __uint_as_float(r[4 * q + 2]);
                v.w = __uint_as_float(r[4 * q + 3]);
                *(float4*)(orow + base + 4 * q) = v;
            }
        }
    }
    asm volatile("tcgen05.fence::before_thread_sync;" ::: "memory");
    __syncthreads();
    if (tid < 32) {
        asm volatile("tcgen05.dealloc.cta_group::1.sync.aligned.b32 %0, %1;"
                     :: "r"(tmem), "r"((uint32_t)NTILE));
    }
#else
    float* smf = (float*)dsm;
    const int wid = tid >> 5, lane = tid & 31;
    const int wm = wid >> 1, wn = wid & 1;
    const int NKT16 = NKT * 2;

    for (int nh = 0; nh < NTILE / 128; nh++) {
        const int n0h = n0 + nh * 128;
        float c[2][8][4] = {};
#pragma unroll 1
        for (int s = 0; s < 2; s++) {
            int k0 = s * 16;
            const float* Ag = (k0 < KSPLIT) ? A0 + (size_t)m0 * LDA0 + k0
                                            : A1 + (size_t)m0 * LDA1 + (k0 - KSPLIT);
            int lda = (k0 < KSPLIT) ? LDA0 : LDA1;
            const float* Bg = (k0 < KSPLIT) ? B0 + (size_t)n0h * LDB0 + k0
                                            : B1 + (size_t)n0h * LDB1 + (k0 - KSPLIT);
            int ldb = (k0 < KSPLIT) ? LDB0 : LDB1;
            load_tile(smf + s * STAGE_FLOATS, Ag, lda);
            load_tile(smf + s * STAGE_FLOATS + 128 * SST, Bg, ldb);
            cp_commit();
        }
#pragma unroll 1
        for (int t = 0; t < NKT16; t++) {
            if (t + 2 < NKT16) cp_wait<1>(); else cp_wait<0>();
            __syncthreads();
            if (t + 2 < NKT16) {
                int k0 = (t + 2) * 16;
                float* sb = smf + ((t + 2) % 3) * STAGE_FLOATS;
                const float* Ag = (k0 < KSPLIT) ? A0 + (size_t)m0 * LDA0 + k0
                                                : A1 + (size_t)m0 * LDA1 + (k0 - KSPLIT);
                int lda = (k0 < KSPLIT) ? LDA0 : LDA1;
                const float* Bg = (k0 < KSPLIT) ? B0 + (size_t)n0h * LDB0 + k0
                                                : B1 + (size_t)n0h * LDB1 + (k0 - KSPLIT);
                int ldb = (k0 < KSPLIT) ? LDB0 : LDB1;
                load_tile(sb, Ag, lda);
                load_tile(sb + 128 * SST, Bg, ldb);
                cp_commit();
            }
            const float* st = smf + (t % 3) * STAGE_FLOATS;
            mma_tile(c, st, st + 128 * SST, wm, wn, lane);
        }
        __syncthreads();

        const int g = lane >> 2, tq = lane & 3;
#pragma unroll
        for (int mi = 0; mi < 2; mi++)
#pragma unroll
            for (int ni = 0; ni < 8; ni++) {
                int col = n0h + wn * 64 + ni * 8 + 2 * tq;
#pragma unroll
                for (int hf = 0; hf < 2; hf++) {
                    int row = m0 + wm * 32 + mi * 16 + hf * 8 + g;
                    float2 o;
                    o.x = c[mi][ni][hf * 2 + 0];
                    o.y = c[mi][ni][hf * 2 + 1];
                    if (ROUND) { o.x = rna_tf32(o.x); o.y = rna_tf32(o.y); }
                    *(float2*)(out + (size_t)row * ldOut + col) = o;
                }
            }
    }
#endif
}

// ---------------- cg2 main GEMM: pair tile M=256 x N=512, K split at KSPLIT ----------------
template <int NKT, int KSPLIT, int LDA0, int LDA1, int LDB0, int LDB1>
__global__ void __launch_bounds__(256, 1) __cluster_dims__(2, 1, 1)
gemm_2cta(const float* __restrict__ A0, const float* __restrict__ A1,
          const float* __restrict__ B0, const float* __restrict__ B1,
          float* __restrict__ out, int ldOut)
{
    extern __shared__ __align__(16) char dsm[];
    const int tid = threadIdx.x;

#if TC_OK
    constexpr int NS = 4;
    constexpr int TILE16K = 16384;
    constexpr int STAGE = 3 * TILE16K;
    const uint32_t sbase = (smem_u32(dsm) + 1023u) & ~1023u;

    __shared__ __align__(8) uint64_t mbar[3 * NS + 1];
    __shared__ uint32_t tmem_slot[1];

    const uint32_t rank = ctarank();
    const int m0 = (blockIdx.x >> 1) * 256 + (int)rank * 128;
    const int n0 = blockIdx.y * 512;

    const uint32_t fullL  = smem_u32(&mbar[0]);
    const uint32_t full2  = smem_u32(&mbar[NS]);
    const uint32_t emptyA = smem_u32(&mbar[2 * NS]);
    const uint32_t doneA  = smem_u32(&mbar[3 * NS]);

    if (tid < 32) {
        asm volatile("tcgen05.alloc.cta_group::2.sync.aligned.shared::cta.b32 [%0], %1;"
                     :: "r"(smem_u32(tmem_slot)), "r"(512u) : "memory");
    }
    if (tid == 0) {
#pragma unroll
        for (int s = 0; s < NS; s++) {
            mbar_init(fullL  + 8 * s, 128);
            mbar_init(full2  + 8 * s, 2);
            mbar_init(emptyA + 8 * s, 1);
        }
        mbar_init(doneA, 1);
    }
    __syncthreads();
    const uint32_t tmem = tmem_slot[0];
    cluster_sync();

    if (tid < 128) {
        // ---------------- producers ----------------
        for (int u = 0; u < NKT; u++) {
            const int s = u & (NS - 1);
            if (u >= NS) mbar_wait(emptyA + 8 * s, ((u / NS) - 1) & 1);
            const int k0 = u * 32;
            const float* Asrc; int lda;
            const float* Bsel; int ldb; int koff;
            if (k0 < KSPLIT) { Asrc = A0 + (size_t)m0 * LDA0 + k0; lda = LDA0;
                               Bsel = B0; ldb = LDB0; koff = k0; }
            else             { Asrc = A1 + (size_t)m0 * LDA1 + (k0 - KSPLIT); lda = LDA1;
                               Bsel = B1; ldb = LDB1; koff = k0 - KSPLIT; }
            const uint32_t sa = sbase + s * STAGE;
#pragma unroll
            for (int c = 0; c < 8; c++) {
                int i = tid + c * 128;
                int row = i >> 3, kc = i & 7;
                cp16(sa + swz(row * 128 + kc * 16), Asrc + (size_t)row * lda + kc * 4);
            }
#pragma unroll
            for (int r = 0; r < 2; r++) {
                const float* Bg = Bsel + (size_t)(n0 + r * 256 + (int)rank * 128) * ldb + koff;
                const uint32_t sb = sa + TILE16K + r * TILE16K;
#pragma unroll
                for (int c = 0; c < 8; c++) {
                    int i = tid + c * 128;
                    int row = i >> 3, kc = i & 7;
                    cp16(sb + swz(row * 128 + kc * 16), Bg + (size_t)row * ldb + kc * 4);
                }
            }
            cp_arrive(fullL + 8 * s);
        }
    } else if (tid == 128) {
        // ---------------- forwarder: local ready -> leader's full2 ----------------
        for (int t = 0; t < NKT; t++) {
            const int s = t & (NS - 1);
            mbar_wait(fullL + 8 * s, (t / NS) & 1);
            asm volatile("fence.proxy.async;" ::: "memory");
            asm volatile(
                "{\n\t.reg .b32 ra;\n\t"
                "mapa.shared::cluster.u32 ra, %0, %1;\n\t"
                "mbarrier.arrive.shared::cluster.b64 _, [ra];\n\t}"
                :: "r"(full2 + 8 * s), "r"(0) : "memory");
        }
    } else if (tid == 160 && rank == 0) {
        // ---------------- MMA issuer (leader) ----------------
        asm volatile("tcgen05.fence::after_thread_sync;" ::: "memory");
        const uint32_t idesc = (1u << 4) | (2u << 7) | (2u << 10) |
                               ((256u / 8) << 17) | ((256u / 16) << 24);
        for (int t = 0; t < NKT; t++) {
            const int s = t & (NS - 1);
            mbar_wait(full2 + 8 * s, (t / NS) & 1);
            const uint64_t ad = mk_desc(sbase + s * STAGE);
#pragma unroll
            for (int r = 0; r < 2; r++) {
                const uint64_t bd = mk_desc(sbase + s * STAGE + TILE16K + r * TILE16K);
#pragma unroll
                for (int k = 0; k < 4; k++)
                    mma_tf32_ss2(tmem + r * 256, ad + 2 * k, bd + 2 * k, idesc,
                                 !(t == 0 && k == 0));
            }
            tc_commit_mc2(emptyA + 8 * s);
        }
        tc_commit_mc2(doneA);
    }

    // ---------------- epilogue ----------------
    mbar_wait(doneA, 0);
    asm volatile("tcgen05.fence::after_thread_sync;" ::: "memory");

    if (tid < 128) {
        float* orow = out + (size_t)(m0 + tid) * ldOut + n0;
#pragma unroll
        for (int base = 0; base < 512; base += 32) {
            uint32_t r[32];
            ldtm32(r, tmem + base);
#pragma unroll
            for (int q = 0; q < 8; q++) {
                float4 v;
                v.x = __uint_as_float(r[4 * q + 0]);
                v.y = __uint_as_float(r[4 * q + 1]);
                v.z = __uint_as_float(r[4 * q + 2]);
                v.w = __uint_as_float(r[4 * q + 3]);
                *(float4*)(orow + base + 4 * q) = v;
            }
        }
    }
    asm volatile("tcgen05.fence::before_thread_sync;" ::: "memory");
    __syncthreads();
    cluster_sync();
    if (tid < 32) {
        asm volatile("tcgen05.relinquish_alloc_permit.cta_group::2.sync.aligned;");
        asm volatile("tcgen05.dealloc.cta_group::2.sync.aligned.b32 %0, %1;"
                     :: "r"(tmem), "r"(512u));
    }
    cluster_sync();
#else
    // ---------------- fallback: mma.sync ----------------
    float* smf = (float*)dsm;
    const int m0 = blockIdx.x * 128;
    const int n0 = blockIdx.y * 512;
    const int wid = tid >> 5, lane = tid & 31;
    const int wm = wid >> 1, wn = wid & 1;
    const int NKT16 = NKT * 2;

    for (int nh = 0; nh < 4; nh++) {
        const int n0h = n0 + nh * 128;
        float c[2][8][4] = {};
#pragma unroll 1
        for (int s = 0; s < 2; s++) {
            int k0 = s * 16;
            const float* Ag = (k0 < KSPLIT) ? A0 + (size_t)m0 * LDA0 + k0
                                            : A1 + (size_t)m0 * LDA1 + (k0 - KSPLIT);
            int lda = (k0 < KSPLIT) ? LDA0 : LDA1;
            const float* Bg = (k0 < KSPLIT) ? B0 + (size_t)n0h * LDB0 + k0
                                            : B1 + (size_t)n0h * LDB1 + (k0 - KSPLIT);
            int ldb = (k0 < KSPLIT) ? LDB0 : LDB1;
            load_tile(smf + s * STAGE_FLOATS, Ag, lda);
            load_tile(smf + s * STAGE_FLOATS + 128 * SST, Bg, ldb);
            cp_commit();
        }
#pragma unroll 1
        for (int t = 0; t < NKT16; t++) {
            if (t + 2 < NKT16) cp_wait<1>(); else cp_wait<0>();
            __syncthreads();
            if (t + 2 < NKT16) {
                int k0 = (t + 2) * 16;
                float* sb = smf + ((t + 2) % 3) * STAGE_FLOATS;
                const float* Ag = (k0 < KSPLIT) ? A0 + (size_t)m0 * LDA0 + k0
                                                : A1 + (size_t)m0 * LDA1 + (k0 - KSPLIT);
                int lda = (k0 < KSPLIT) ? LDA0 : LDA1;
                const float* Bg = (k0 < KSPLIT) ? B0 + (size_t)n0h * LDB0 + k0
                                                : B1 + (size_t)n0h * LDB1 + (k0 - KSPLIT);
                int ldb = (k0 < KSPLIT) ? LDB0 : LDB1;
                load_tile(sb, Ag, lda);
                load_tile(sb + 128 * SST, Bg, ldb);
                cp_commit();
            }
            const float* st = smf + (t % 3) * STAGE_FLOATS;
            mma_tile(c, st, st + 128 * SST, wm, wn, lane);
        }
        __syncthreads();

        const int g = lane >> 2, tq = lane & 3;
#pragma unroll
        for (int mi = 0; mi < 2; mi++)
#pragma unroll
            for (int ni = 0; ni < 8; ni++) {
                int col = n0h + wn * 64 + ni * 8 + 2 * tq;
#pragma unroll
                for (int hf = 0; hf < 2; hf++) {
                    int row = m0 + wm * 32 + mi * 16 + hf * 8 + g;
                    float2 o;
                    o.x = c[mi][ni][hf * 2 + 0];
                    o.y = c[mi][ni][hf * 2 + 1];
                    *(float2*)(out + (size_t)row * ldOut + col) = o;
                }
            }
    }
#endif
}

// ---------------- launch ----------------
extern "C" void kernel_launch(void* const* d_in, const int* in_sizes, int n_in,
                              void* d_out, int out_size) {
    const float* x         = (const float*)d_in[0];
    const float* h_prev    = (const float*)d_in[1];
    const float* Br        = (const float*)d_in[2];
    const float* Bi        = (const float*)d_in[3];
    const float* Cr        = (const float*)d_in[4];
    const float* Ci        = (const float*)d_in[5];
    const float* v_log     = (const float*)d_in[6];
    const float* theta_log = (const float*)d_in[7];

    float *p_Crr, *p_Cir, *p_BrT, *p_BiTn, *p_E, *p_D;
    cudaGetSymbolAddress((void**)&p_Crr,  g_Crr);
    cudaGetSymbolAddress((void**)&p_Cir,  g_Cir);
    cudaGetSymbolAddress((void**)&p_BrT,  g_BrT);
    cudaGetSymbolAddress((void**)&p_BiTn, g_BiTn);
    cudaGetSymbolAddress((void**)&p_E,    g_E);
    cudaGetSymbolAddress((void**)&p_D,    g_D);

    // fold: E = [Cr|Ci] @ [BrT|-BiT]^T   (M=1024, N=1024, K=4096)
    auto* foldK = gemm_tc<128, 128, 2048, 2048, 2048, 2048, 2048, true>;
    // main: out = [hp|x] @ [D|E]^T       (M=8192, N=1024, K=3072)
    auto* mainK = gemm_2cta<96, 2048, 2048, 1024, 2048, 1024>;

    const int smem_fold = 4 * (128 * 128 + 128 * 128) + 1024;   // 132 KB
    const int smem_main = 4 * (3 * 16384) + 1024;               // 197632 B
    cudaFuncSetAttribute(foldK, cudaFuncAttributeMaxDynamicSharedMemorySize, smem_fold);
    cudaFuncSetAttribute(mainK, cudaFuncAttributeMaxDynamicSharedMemorySize, smem_main);

    // launch 0: merged prep (transposes + fused Cr/Ci rounding + D, w hoisted)
    prep_all<<<4224, 256>>>(Br, Bi, (const float4*)Cr, (const float4*)Ci, v_log, theta_log);

    // launch 1: fold GEMM
    foldK<<<dim3(OUT_DIM / 128, IN_DIM / 128), 256, smem_fold>>>(p_Crr, p_Cir, p_BrT, p_BiTn,
                                                                 p_E, IN_DIM);

    // launch 2: main GEMM — grid (64, 2), cluster (2,1,1)
    mainK<<<dim3(2 * (BQ / 256), OUT_DIM / 512), 256, smem_main>>>(h_prev, x, p_D, p_E,
                                                                   (float*)d_out, OUT_DIM);
}

// round 11
// speedup vs baseline: 1.5903x; 1.5061x over previous
#include <cuda_runtime.h>
#include <cstdint>
#include <cstddef>

#define BQ      8192
#define IN_DIM  1024
#define H_DIM   2048
#define OUT_DIM 1024

#if defined(__CUDA_ARCH_FEAT_SM103_ALL) || defined(__CUDA_ARCH_FEAT_SM100_ALL)
#define TC_OK 1
#else
#define TC_OK 0
#endif

// ---------------- scratch ----------------
__device__ float g_Crr [(size_t)OUT_DIM * H_DIM];   // RNA tf32 Cr
__device__ float g_Cir [(size_t)OUT_DIM * H_DIM];   // RNA tf32 Ci
__device__ float g_BrT [(size_t)IN_DIM * H_DIM];    // Br^T, RNA tf32
__device__ float g_BiTn[(size_t)IN_DIM * H_DIM];    // -Bi^T, RNA tf32
__device__ float g_E   [(size_t)OUT_DIM * IN_DIM];  // Cr@Br - Ci@Bi, RNA tf32
__device__ float g_D   [(size_t)OUT_DIM * H_DIM];   // wr.*Cr - wi.*Ci, RNA tf32

// ---------------- helpers ----------------
__device__ __forceinline__ float rna_tf32(float x) {
    uint32_t r;
    asm("cvt.rna.tf32.f32 %0, %1;" : "=r"(r) : "f"(x));
    return __uint_as_float(r);
}
__device__ __forceinline__ uint32_t smem_u32(const void* p) {
    return (uint32_t)__cvta_generic_to_shared(p);
}
__device__ __forceinline__ void cp16(uint32_t dst, const void* src) {
    asm volatile("cp.async.cg.shared.global [%0], [%1], 16;" :: "r"(dst), "l"(src));
}
__device__ __forceinline__ void cp_commit() { asm volatile("cp.async.commit_group;"); }
template <int N> __device__ __forceinline__ void cp_wait() {
    asm volatile("cp.async.wait_group %0;" :: "n"(N));
}
__device__ __forceinline__ uint32_t swz(uint32_t off) {   // SW128
    return off ^ ((off >> 3) & 0x70);
}
__device__ __forceinline__ void mbar_init(uint32_t addr, uint32_t cnt) {
    asm volatile("mbarrier.init.shared.b64 [%0], %1;" :: "r"(addr), "r"(cnt) : "memory");
}
__device__ __forceinline__ void mbar_wait(uint32_t addr, uint32_t parity) {
    asm volatile(
        "{\n\t.reg .pred P;\n\t"
        "W%=:\n\t"
        "mbarrier.try_wait.parity.shared::cta.b64 P, [%0], %1, 0x989680;\n\t"
        "@!P bra W%=;\n\t"
        "}" :: "r"(addr), "r"(parity) : "memory");
}
__device__ __forceinline__ void cp_arrive(uint32_t addr) {
    asm volatile("cp.async.mbarrier.arrive.noinc.shared::cta.b64 [%0];" :: "r"(addr) : "memory");
}
__device__ __forceinline__ void cluster_sync() {
    asm volatile("barrier.cluster.arrive.aligned;" ::: "memory");
    asm volatile("barrier.cluster.wait.aligned;" ::: "memory");
}
__device__ __forceinline__ uint32_t ctarank() {
    uint32_t r;
    asm("mov.u32 %0, %%cluster_ctarank;" : "=r"(r));
    return r;
}
// mma.sync fallback helpers
__device__ __forceinline__ void ldm4(uint32_t& r0, uint32_t& r1, uint32_t& r2, uint32_t& r3, uint32_t a) {
    asm volatile("ldmatrix.sync.aligned.m8n8.x4.shared.b16 {%0,%1,%2,%3}, [%4];"
                 : "=r"(r0), "=r"(r1), "=r"(r2), "=r"(r3) : "r"(a));
}
__device__ __forceinline__ void mma8(float* c, const uint32_t* a, uint32_t b0, uint32_t b1) {
    asm volatile("mma.sync.aligned.m16n8k8.row.col.f32.tf32.tf32.f32 "
                 "{%0,%1,%2,%3}, {%4,%5,%6,%7}, {%8,%9}, {%0,%1,%2,%3};"
                 : "+f"(c[0]), "+f"(c[1]), "+f"(c[2]), "+f"(c[3])
                 : "r"(a[0]), "r"(a[1]), "r"(a[2]), "r"(a[3]), "r"(b0), "r"(b1));
}

#define SST 20
#define STAGE_FLOATS (2 * 128 * SST)

__device__ __forceinline__ void load_tile(float* s, const float* g, int ld) {
#pragma unroll
    for (int c = 0; c < 2; c++) {
        int idx = threadIdx.x + c * 256;
        int row = idx >> 2;
        int kc  = (idx & 3) << 2;
        cp16(smem_u32(s + row * SST + kc), g + (size_t)row * ld + kc);
    }
}
__device__ __forceinline__ void mma_tile(float c[2][8][4], const float* As, const float* Bs,
                                         int wm, int wn, int lane) {
#pragma unroll
    for (int ks = 0; ks < 2; ks++) {
        const int k0 = ks * 8;
        uint32_t af[2][4];
        const int ar = (lane & 7) + ((lane >> 3) & 1) * 8;
        const int ac = k0 + (lane >> 4) * 4;
#pragma unroll
        for (int mi = 0; mi < 2; mi++) {
            uint32_t addr = smem_u32(As + (wm * 32 + mi * 16 + ar) * SST + ac);
            ldm4(af[mi][0], af[mi][1], af[mi][2], af[mi][3], addr);
        }
        const int br = (lane & 7) + ((lane >> 4) ? 8 : 0);
        const int bc = k0 + ((lane >> 3) & 1) * 4;
#pragma unroll
        for (int p = 0; p < 4; p++) {
            uint32_t b0, b1, b2, b3;
            uint32_t addr = smem_u32(Bs + (wn * 64 + p * 16 + br) * SST + bc);
            ldm4(b0, b1, b2, b3, addr);
#pragma unroll
            for (int mi = 0; mi < 2; mi++) {
                mma8(c[mi][2 * p],     af[mi], b0, b1);
                mma8(c[mi][2 * p + 1], af[mi], b2, b3);
            }
        }
    }
}

#if TC_OK
__device__ __forceinline__ void tc_commit(uint32_t mbar) {
    asm volatile("tcgen05.commit.cta_group::1.mbarrier::arrive::one.shared::cluster.b64 [%0];"
                 :: "r"(mbar) : "memory");
}
__device__ __forceinline__ void tc_commit_mc2(uint32_t mbar) {
    asm volatile(
        "tcgen05.commit.cta_group::2.mbarrier::arrive::one.shared::cluster.multicast::cluster.b64 [%0], %1;"
        :: "r"(mbar), "h"((uint16_t)3) : "memory");
}
__device__ __forceinline__ void mma_tf32_ss(uint32_t d_tmem, uint64_t a_desc, uint64_t b_desc,
                                            uint32_t idesc, bool enable) {
    uint32_t en = enable ? 1u : 0u;
    asm volatile(
        "{\n\t.reg .pred p;\n\t"
        "setp.ne.u32 p, %4, 0;\n\t"
        "tcgen05.mma.cta_group::1.kind::tf32 [%0], %1, %2, %3, {%5,%5,%5,%5}, p;\n\t}"
        :: "r"(d_tmem), "l"(a_desc), "l"(b_desc), "r"(idesc), "r"(en), "r"(0u) : "memory");
}
__device__ __forceinline__ void mma_tf32_ss2(uint32_t d_tmem, uint64_t a_desc, uint64_t b_desc,
                                             uint32_t idesc, bool enable) {
    uint32_t en = enable ? 1u : 0u;
    asm volatile(
        "{\n\t.reg .pred p;\n\t"
        "setp.ne.u32 p, %4, 0;\n\t"
        "tcgen05.mma.cta_group::2.kind::tf32 [%0], %1, %2, %3, {%5,%5,%5,%5,%5,%5,%5,%5}, p;\n\t}"
        :: "r"(d_tmem), "l"(a_desc), "l"(b_desc), "r"(idesc), "r"(en), "r"(0u) : "memory");
}
__device__ __forceinline__ uint64_t mk_desc(uint32_t addr) {
    return ((uint64_t)2 << 61) | ((uint64_t)1 << 46) | ((uint64_t)64 << 32) |
           ((uint64_t)1 << 16) | (((uint64_t)addr >> 4) & 0x3FFF);
}
__device__ __forceinline__ void ldtm32(uint32_t* r, uint32_t addr) {
    asm volatile(
        "tcgen05.ld.sync.aligned.32x32b.x32.b32 "
        "{%0,%1,%2,%3,%4,%5,%6,%7,%8,%9,%10,%11,%12,%13,%14,%15,"
        "%16,%17,%18,%19,%20,%21,%22,%23,%24,%25,%26,%27,%28,%29,%30,%31}, [%32];"
        : "=r"(r[0]), "=r"(r[1]), "=r"(r[2]), "=r"(r[3]),
          "=r"(r[4]), "=r"(r[5]), "=r"(r[6]), "=r"(r[7]),
          "=r"(r[8]), "=r"(r[9]), "=r"(r[10]), "=r"(r[11]),
          "=r"(r[12]), "=r"(r[13]), "=r"(r[14]), "=r"(r[15]),
          "=r"(r[16]), "=r"(r[17]), "=r"(r[18]), "=r"(r[19]),
          "=r"(r[20]), "=r"(r[21]), "=r"(r[22]), "=r"(r[23]),
          "=r"(r[24]), "=r"(r[25]), "=r"(r[26]), "=r"(r[27]),
          "=r"(r[28]), "=r"(r[29]), "=r"(r[30]), "=r"(r[31])
        : "r"(addr));
    asm volatile("tcgen05.wait::ld.sync.aligned;" ::: "memory");
}
#endif

// ---------------- merged prep ----------------
// grid 6144 x 256:
//   [0,2048)    BrT  (transpose + RNA)
//   [2048,4096) BiTn (transpose + negate + RNA)
//   [4096,6144) fused: round Cr,Ci -> Crr,Cir AND D, w via fast intrinsics
//               (w error ~2^-21 << tf32 rounding 2^-11; D is rna_tf32'd anyway)
__global__ void prep_all(const float* __restrict__ Br, const float* __restrict__ Bi,
                         const float4* __restrict__ Cr4, const float4* __restrict__ Ci4,
                         const float* __restrict__ v_log, const float* __restrict__ theta_log) {
    const int b = blockIdx.x;
    if (b < 4096) {
        __shared__ float tile[32][33];
        const float* src = (b < 2048) ? Br : Bi;
        float* dst = (b < 2048) ? g_BrT : g_BiTn;
        const float sign = (b < 2048) ? 1.0f : -1.0f;
        const int lb = b & 2047;
        const int bx = lb & 31;
        const int by = lb >> 5;
        const int tx = threadIdx.x & 31, ty = threadIdx.x >> 5;
        const int cx = bx * 32 + tx;
        const int ry = by * 32 + ty;
#pragma unroll
        for (int j = 0; j < 32; j += 8)
            tile[ty + j][tx] = src[(size_t)(ry + j) * IN_DIM + cx];
        __syncthreads();
        const int ox = by * 32 + tx;
        const int oy = bx * 32 + ty;
#pragma unroll
        for (int j = 0; j < 32; j += 8)
            dst[(size_t)(oy + j) * H_DIM + ox] = rna_tf32(sign * tile[tx][ty + j]);
    } else {
        int i = (b - 4096) * 256 + threadIdx.x;       // float4 index over [OUT, H]
        int h0 = (i & (H_DIM / 4 - 1)) * 4;
        float4 cr = Cr4[i], ci = Ci4[i];
        float4 rr, ri;
        rr.x = rna_tf32(cr.x); rr.y = rna_tf32(cr.y);
        rr.z = rna_tf32(cr.z); rr.w = rna_tf32(cr.w);
        ri.x = rna_tf32(ci.x); ri.y = rna_tf32(ci.y);
        ri.z = rna_tf32(ci.z); ri.w = rna_tf32(ci.w);
        ((float4*)g_Crr)[i] = rr;
        ((float4*)g_Cir)[i] = ri;
        const float* c4r = (const float*)&cr;
        const float* c4i = (const float*)&ci;
        float o[4];
#pragma unroll
        for (int k = 0; k < 4; k++) {
            float mag = __expf(-__expf(v_log[h0 + k]));
            float ang = __expf(theta_log[h0 + k]);
            float sn, cs;
            __sincosf(ang, &sn, &cs);
            o[k] = rna_tf32(mag * cs * c4r[k] - mag * sn * c4i[k]);
        }
        ((float4*)g_D)[i] = make_float4(o[0], o[1], o[2], o[3]);
    }
}

// ---------------- cg1 GEMM (fold): out[128*gx, NTILE*gy] = A @ B^T ----------------
template <int NTILE, int NKT, int KSPLIT, int LDA0, int LDA1, int LDB0, int LDB1, bool ROUND>
__global__ void __launch_bounds__(256, 1) gemm_tc(
    const float* __restrict__ A0, const float* __restrict__ A1,
    const float* __restrict__ B0, const float* __restrict__ B1,
    float* __restrict__ out, int ldOut)
{
    extern __shared__ __align__(16) char dsm[];
    const int tid = threadIdx.x;
    const int m0 = blockIdx.x * 128;
    const int n0 = blockIdx.y * NTILE;

#if TC_OK
    constexpr int NS = 4;
    constexpr int ABYTES = 128 * 128;
    constexpr int STAGE  = ABYTES + NTILE * 128;
    const uint32_t sbase = (smem_u32(dsm) + 1023u) & ~1023u;

    __shared__ __align__(8) uint64_t mbar[2 * NS + 1];
    __shared__ uint32_t tmem_slot[1];

    const uint32_t fullA  = smem_u32(&mbar[0]);
    const uint32_t emptyA = smem_u32(&mbar[NS]);
    const uint32_t doneA  = smem_u32(&mbar[2 * NS]);

    if (tid < 32) {
        asm volatile("tcgen05.alloc.cta_group::1.sync.aligned.shared::cta.b32 [%0], %1;"
                     :: "r"(smem_u32(tmem_slot)), "r"((uint32_t)NTILE) : "memory");
    }
    if (tid == 0) {
#pragma unroll
        for (int s = 0; s < NS; s++) {
            mbar_init(fullA  + 8 * s, 128);
            mbar_init(emptyA + 8 * s, 1);
        }
        mbar_init(doneA, 1);
    }
    __syncthreads();
    const uint32_t tmem = tmem_slot[0];

    if (tid < 128) {
        for (int u = 0; u < NKT; u++) {
            const int s = u & (NS - 1);
            if (u >= NS) mbar_wait(emptyA + 8 * s, ((u / NS) - 1) & 1);
            const int k0 = u * 32;
            const float* Ag; int lda;
            const float* Bg; int ldb;
            if (k0 < KSPLIT) { Ag = A0 + (size_t)m0 * LDA0 + k0; lda = LDA0; }
            else             { Ag = A1 + (size_t)m0 * LDA1 + (k0 - KSPLIT); lda = LDA1; }
            if (k0 < KSPLIT) { Bg = B0 + (size_t)n0 * LDB0 + k0; ldb = LDB0; }
            else             { Bg = B1 + (size_t)n0 * LDB1 + (k0 - KSPLIT); ldb = LDB1; }
            const uint32_t sa = sbase + s * STAGE;
            const uint32_t sb = sa + ABYTES;
#pragma unroll
            for (int c = 0; c < 8; c++) {
                int i = tid + c * 128;
                int row = i >> 3, kc = i & 7;
                cp16(sa + swz(row * 128 + kc * 16), Ag + (size_t)row * lda + kc * 4);
            }
#pragma unroll
            for (int c = 0; c < NTILE / 16; c++) {
                int i = tid + c * 128;
                int row = i >> 3, kc = i & 7;
                cp16(sb + swz(row * 128 + kc * 16), Bg + (size_t)row * ldb + kc * 4);
            }
            cp_arrive(fullA + 8 * s);
        }
    } else if (tid == 128) {
        asm volatile("tcgen05.fence::after_thread_sync;" ::: "memory");
        const uint32_t idesc = (1u << 4) | (2u << 7) | (2u << 10) |
                               ((uint32_t)(NTILE / 8) << 17) | (8u << 24);
        for (int t = 0; t < NKT; t++) {
            const int s = t & (NS - 1);
            mbar_wait(fullA + 8 * s, (t / NS) & 1);
            asm volatile("fence.proxy.async.shared::cta;" ::: "memory");
            const uint64_t ad = mk_desc(sbase + s * STAGE);
            const uint64_t bd = mk_desc(sbase + s * STAGE + ABYTES);
#pragma unroll
            for (int k = 0; k < 4; k++)
                mma_tf32_ss(tmem, ad + 2 * k, bd + 2 * k, idesc, !(t == 0 && k == 0));
            tc_commit(emptyA + 8 * s);
        }
        tc_commit(doneA);
    }

    mbar_wait(doneA, 0);
    asm volatile("tcgen05.fence::after_thread_sync;" ::: "memory");

    if (tid < 128) {
        float* orow = out + (size_t)(m0 + tid) * ldOut + n0;
#pragma unroll
        for (int base = 0; base < NTILE; base += 32) {
            uint32_t r[32];
            ldtm32(r, tmem + base);
            if (ROUND) {
#pragma unroll
                for (int i = 0; i < 32; i++)
                    r[i] = __float_as_uint(rna_tf32(__uint_as_float(r[i])));
            }
#pragma unroll
            for (int q = 0; q < 8; q++) {
                float4 v;
                v.x = __uint_as_float(r[4 * q + 0]);
                v.y = __uint_as_float(r[4 * q + 1]);
                v.z = __uint_as_float(r[4 * q + 2]);
                v.w = __uint_as_float(r[4 * q + 3]);
                *(float4*)(orow + base + 4 * q) = v;
            }
        }
    }
    asm volatile("tcgen05.fence::before_thread_sync;" ::: "memory");
    __syncthreads();
    if (tid < 32) {
        asm volatile("tcgen05.dealloc.cta_group::1.sync.aligned.b32 %0, %1;"
                     :: "r"(tmem), "r"((uint32_t)NTILE));
    }
#else
    float* smf = (float*)dsm;
    const int wid = tid >> 5, lane = tid & 31;
    const int wm = wid >> 1, wn = wid & 1;
    const int NKT16 = NKT * 2;

    for (int nh = 0; nh < NTILE / 128; nh++) {
        const int n0h = n0 + nh * 128;
        float c[2][8][4] = {};
#pragma unroll 1
        for (int s = 0; s < 2; s++) {
            int k0 = s * 16;
            const float* Ag = (k0 < KSPLIT) ? A0 + (size_t)m0 * LDA0 + k0
                                            : A1 + (size_t)m0 * LDA1 + (k0 - KSPLIT);
            int lda = (k0 < KSPLIT) ? LDA0 : LDA1;
            const float* Bg = (k0 < KSPLIT) ? B0 + (size_t)n0h * LDB0 + k0
                                            : B1 + (size_t)n0h * LDB1 + (k0 - KSPLIT);
            int ldb = (k0 < KSPLIT) ? LDB0 : LDB1;
            load_tile(smf + s * STAGE_FLOATS, Ag, lda);
            load_tile(smf + s * STAGE_FLOATS + 128 * SST, Bg, ldb);
            cp_commit();
        }
#pragma unroll 1
        for (int t = 0; t < NKT16; t++) {
            if (t + 2 < NKT16) cp_wait<1>(); else cp_wait<0>();
            __syncthreads();
            if (t + 2 < NKT16) {
                int k0 = (t + 2) * 16;
                float* sb = smf + ((t + 2) % 3) * STAGE_FLOATS;
                const float* Ag = (k0 < KSPLIT) ? A0 + (size_t)m0 * LDA0 + k0
                                                : A1 + (size_t)m0 * LDA1 + (k0 - KSPLIT);
                int lda = (k0 < KSPLIT) ? LDA0 : LDA1;
                const float* Bg = (k0 < KSPLIT) ? B0 + (size_t)n0h * LDB0 + k0
                                                : B1 + (size_t)n0h * LDB1 + (k0 - KSPLIT);
                int ldb = (k0 < KSPLIT) ? LDB0 : LDB1;
                load_tile(sb, Ag, lda);
                load_tile(sb + 128 * SST, Bg, ldb);
                cp_commit();
            }
            const float* st = smf + (t % 3) * STAGE_FLOATS;
            mma_tile(c, st, st + 128 * SST, wm, wn, lane);
        }
        __syncthreads();

        const int g = lane >> 2, tq = lane & 3;
#pragma unroll
        for (int mi = 0; mi < 2; mi++)
#pragma unroll
            for (int ni = 0; ni < 8; ni++) {
                int col = n0h + wn * 64 + ni * 8 + 2 * tq;
#pragma unroll
                for (int hf = 0; hf < 2; hf++) {
                    int row = m0 + wm * 32 + mi * 16 + hf * 8 + g;
                    float2 o;
                    o.x = c[mi][ni][hf * 2 + 0];
                    o.y = c[mi][ni][hf * 2 + 1];
                    if (ROUND) { o.x = rna_tf32(o.x); o.y = rna_tf32(o.y); }
                    *(float2*)(out + (size_t)row * ldOut + col) = o;
                }
            }
    }
#endif
}

// ---------------- cg2 main GEMM: pair tile M=256 x N=512, K split at KSPLIT ----------------
template <int NKT, int KSPLIT, int LDA0, int LDA1, int LDB0, int LDB1>
__global__ void __launch_bounds__(256, 1) __cluster_dims__(2, 1, 1)
gemm_2cta(const float* __restrict__ A0, const float* __restrict__ A1,
          const float* __restrict__ B0, const float* __restrict__ B1,
          float* __restrict__ out, int ldOut)
{
    extern __shared__ __align__(16) char dsm[];
    const int tid = threadIdx.x;

#if TC_OK
    constexpr int NS = 4;
    constexpr int TILE16K = 16384;
    constexpr int STAGE = 3 * TILE16K;
    const uint32_t sbase = (smem_u32(dsm) + 1023u) & ~1023u;

    __shared__ __align__(8) uint64_t mbar[3 * NS + 1];
    __shared__ uint32_t tmem_slot[1];

    const uint32_t rank = ctarank();
    const int m0 = (blockIdx.x >> 1) * 256 + (int)rank * 128;
    const int n0 = blockIdx.y * 512;

    const uint32_t fullL  = smem_u32(&mbar[0]);
    const uint32_t full2  = smem_u32(&mbar[NS]);
    const uint32_t emptyA = smem_u32(&mbar[2 * NS]);
    const uint32_t doneA  = smem_u32(&mbar[3 * NS]);

    if (tid < 32) {
        asm volatile("tcgen05.alloc.cta_group::2.sync.aligned.shared::cta.b32 [%0], %1;"
                     :: "r"(smem_u32(tmem_slot)), "r"(512u) : "memory");
    }
    if (tid == 0) {
#pragma unroll
        for (int s = 0; s < NS; s++) {
            mbar_init(fullL  + 8 * s, 128);
            mbar_init(full2  + 8 * s, 2);
            mbar_init(emptyA + 8 * s, 1);
        }
        mbar_init(doneA, 1);
    }
    __syncthreads();
    const uint32_t tmem = tmem_slot[0];
    cluster_sync();

    if (tid < 128) {
        // ---------------- producers ----------------
        for (int u = 0; u < NKT; u++) {
            const int s = u & (NS - 1);
            if (u >= NS) mbar_wait(emptyA + 8 * s, ((u / NS) - 1) & 1);
            const int k0 = u * 32;
            const float* Asrc; int lda;
            const float* Bsel; int ldb; int koff;
            if (k0 < KSPLIT) { Asrc = A0 + (size_t)m0 * LDA0 + k0; lda = LDA0;
                               Bsel = B0; ldb = LDB0; koff = k0; }
            else             { Asrc = A1 + (size_t)m0 * LDA1 + (k0 - KSPLIT); lda = LDA1;
                               Bsel = B1; ldb = LDB1; koff = k0 - KSPLIT; }
            const uint32_t sa = sbase + s * STAGE;
#pragma unroll
            for (int c = 0; c < 8; c++) {
                int i = tid + c * 128;
                int row = i >> 3, kc = i & 7;
                cp16(sa + swz(row * 128 + kc * 16), Asrc + (size_t)row * lda + kc * 4);
            }
#pragma unroll
            for (int r = 0; r < 2; r++) {
                const float* Bg = Bsel + (size_t)(n0 + r * 256 + (int)rank * 128) * ldb + koff;
                const uint32_t sb = sa + TILE16K + r * TILE16K;
#pragma unroll
                for (int c = 0; c < 8; c++) {
                    int i = tid + c * 128;
                    int row = i >> 3, kc = i & 7;
                    cp16(sb + swz(row * 128 + kc * 16), Bg + (size_t)row * ldb + kc * 4);
                }
            }
            cp_arrive(fullL + 8 * s);
        }
    } else if (tid == 128) {
        // ---------------- forwarder: local ready -> leader's full2 ----------------
        for (int t = 0; t < NKT; t++) {
            const int s = t & (NS - 1);
            mbar_wait(fullL + 8 * s, (t / NS) & 1);
            asm volatile("fence.proxy.async;" ::: "memory");
            asm volatile(
                "{\n\t.reg .b32 ra;\n\t"
                "mapa.shared::cluster.u32 ra, %0, %1;\n\t"
                "mbarrier.arrive.shared::cluster.b64 _, [ra];\n\t}"
                :: "r"(full2 + 8 * s), "r"(0) : "memory");
        }
    } else if (tid == 160 && rank == 0) {
        // ---------------- MMA issuer (leader) ----------------
        asm volatile("tcgen05.fence::after_thread_sync;" ::: "memory");
        const uint32_t idesc = (1u << 4) | (2u << 7) | (2u << 10) |
                               ((256u / 8) << 17) | ((256u / 16) << 24);
        for (int t = 0; t < NKT; t++) {
            const int s = t & (NS - 1);
            mbar_wait(full2 + 8 * s, (t / NS) & 1);
            const uint64_t ad = mk_desc(sbase + s * STAGE);
#pragma unroll
            for (int r = 0; r < 2; r++) {
                const uint64_t bd = mk_desc(sbase + s * STAGE + TILE16K + r * TILE16K);
#pragma unroll
                for (int k = 0; k < 4; k++)
                    mma_tf32_ss2(tmem + r * 256, ad + 2 * k, bd + 2 * k, idesc,
                                 !(t == 0 && k == 0));
            }
            tc_commit_mc2(emptyA + 8 * s);
        }
        tc_commit_mc2(doneA);
    }

    // ---------------- epilogue ----------------
    mbar_wait(doneA, 0);
    asm volatile("tcgen05.fence::after_thread_sync;" ::: "memory");

    if (tid < 128) {
        float* orow = out + (size_t)(m0 + tid) * ldOut + n0;
#pragma unroll
        for (int base = 0; base < 512; base += 32) {
            uint32_t r[32];
            ldtm32(r, tmem + base);
#pragma unroll
            for (int q = 0; q < 8; q++) {
                float4 v;
                v.x = __uint_as_float(r[4 * q + 0]);
                v.y = __uint_as_float(r[4 * q + 1]);
                v.z = __uint_as_float(r[4 * q + 2]);
                v.w = __uint_as_float(r[4 * q + 3]);
                *(float4*)(orow + base + 4 * q) = v;
            }
        }
    }
    asm volatile("tcgen05.fence::before_thread_sync;" ::: "memory");
    __syncthreads();
    cluster_sync();
    if (tid < 32) {
        asm volatile("tcgen05.relinquish_alloc_permit.cta_group::2.sync.aligned;");
        asm volatile("tcgen05.dealloc.cta_group::2.sync.aligned.b32 %0, %1;"
                     :: "r"(tmem), "r"(512u));
    }
    cluster_sync();
#else
    // ---------------- fallback: mma.sync ----------------
    float* smf = (float*)dsm;
    const int m0 = blockIdx.x * 128;
    const int n0 = blockIdx.y * 512;
    const int wid = tid >> 5, lane = tid & 31;
    const int wm = wid >> 1, wn = wid & 1;
    const int NKT16 = NKT * 2;

    for (int nh = 0; nh < 4; nh++) {
        const int n0h = n0 + nh * 128;
        float c[2][8][4] = {};
#pragma unroll 1
        for (int s = 0; s < 2; s++) {
            int k0 = s * 16;
            const float* Ag = (k0 < KSPLIT) ? A0 + (size_t)m0 * LDA0 + k0
                                            : A1 + (size_t)m0 * LDA1 + (k0 - KSPLIT);
            int lda = (k0 < KSPLIT) ? LDA0 : LDA1;
            const float* Bg = (k0 < KSPLIT) ? B0 + (size_t)n0h * LDB0 + k0
                                            : B1 + (size_t)n0h * LDB1 + (k0 - KSPLIT);
            int ldb = (k0 < KSPLIT) ? LDB0 : LDB1;
            load_tile(smf + s * STAGE_FLOATS, Ag, lda);
            load_tile(smf + s * STAGE_FLOATS + 128 * SST, Bg, ldb);
            cp_commit();
        }
#pragma unroll 1
        for (int t = 0; t < NKT16; t++) {
            if (t + 2 < NKT16) cp_wait<1>(); else cp_wait<0>();
            __syncthreads();
            if (t + 2 < NKT16) {
                int k0 = (t + 2) * 16;
                float* sb = smf + ((t + 2) % 3) * STAGE_FLOATS;
                const float* Ag = (k0 < KSPLIT) ? A0 + (size_t)m0 * LDA0 + k0
                                                : A1 + (size_t)m0 * LDA1 + (k0 - KSPLIT);
                int lda = (k0 < KSPLIT) ? LDA0 : LDA1;
                const float* Bg = (k0 < KSPLIT) ? B0 + (size_t)n0h * LDB0 + k0
                                                : B1 + (size_t)n0h * LDB1 + (k0 - KSPLIT);
                int ldb = (k0 < KSPLIT) ? LDB0 : LDB1;
                load_tile(sb, Ag, lda);
                load_tile(sb + 128 * SST, Bg, ldb);
                cp_commit();
            }
            const float* st = smf + (t % 3) * STAGE_FLOATS;
            mma_tile(c, st, st + 128 * SST, wm, wn, lane);
        }
        __syncthreads();

        const int g = lane >> 2, tq = lane & 3;
#pragma unroll
        for (int mi = 0; mi < 2; mi++)
#pragma unroll
            for (int ni = 0; ni < 8; ni++) {
                int col = n0h + wn * 64 + ni * 8 + 2 * tq;
#pragma unroll
                for (int hf = 0; hf < 2; hf++) {
                    int row = m0 + wm * 32 + mi * 16 + hf * 8 + g;
                    float2 o;
                    o.x = c[mi][ni][hf * 2 + 0];
                    o.y = c[mi][ni][hf * 2 + 1];
                    *(float2*)(out + (size_t)row * ldOut + col) = o;
                }
            }
    }
#endif
}

// ---------------- launch ----------------
extern "C" void kernel_launch(void* const* d_in, const int* in_sizes, int n_in,
                              void* d_out, int out_size) {
    const float* x         = (const float*)d_in[0];
    const float* h_prev    = (const float*)d_in[1];
    const float* Br        = (const float*)d_in[2];
    const float* Bi        = (const float*)d_in[3];
    const float* Cr        = (const float*)d_in[4];
    const float* Ci        = (const float*)d_in[5];
    const float* v_log     = (const float*)d_in[6];
    const float* theta_log = (const float*)d_in[7];

    float *p_Crr, *p_Cir, *p_BrT, *p_BiTn, *p_E, *p_D;
    cudaGetSymbolAddress((void**)&p_Crr,  g_Crr);
    cudaGetSymbolAddress((void**)&p_Cir,  g_Cir);
    cudaGetSymbolAddress((void**)&p_BrT,  g_BrT);
    cudaGetSymbolAddress((void**)&p_BiTn, g_BiTn);
    cudaGetSymbolAddress((void**)&p_E,    g_E);
    cudaGetSymbolAddress((void**)&p_D,    g_D);

    // fold: E = [Cr|Ci] @ [BrT|-BiT]^T   (M=1024, N=1024, K=4096)
    auto* foldK = gemm_tc<128, 128, 2048, 2048, 2048, 2048, 2048, true>;
    // main: out = [hp|x] @ [D|E]^T       (M=8192, N=1024, K=3072)
    auto* mainK = gemm_2cta<96, 2048, 2048, 1024, 2048, 1024>;

    const int smem_fold = 4 * (128 * 128 + 128 * 128) + 1024;   // 132 KB
    const int smem_main = 4 * (3 * 16384) + 1024;               // 197632 B
    cudaFuncSetAttribute(foldK, cudaFuncAttributeMaxDynamicSharedMemorySize, smem_fold);
    cudaFuncSetAttribute(mainK, cudaFuncAttributeMaxDynamicSharedMemorySize, smem_main);

    // launch 0: merged prep
    prep_all<<<6144, 256>>>(Br, Bi, (const float4*)Cr, (const float4*)Ci, v_log, theta_log);

    // launch 1: fold GEMM
    foldK<<<dim3(OUT_DIM / 128, IN_DIM / 128), 256, smem_fold>>>(p_Crr, p_Cir, p_BrT, p_BiTn,
                                                                 p_E, IN_DIM);

    // launch 2: main GEMM — grid (64, 2), cluster (2,1,1)
    mainK<<<dim3(2 * (BQ / 256), OUT_DIM / 512), 256, smem_main>>>(h_prev, x, p_D, p_E,
                                                                   (float*)d_out, OUT_DIM);
}

// round 12
// speedup vs baseline: 1.6521x; 1.0388x over previous
#include <cuda_runtime.h>
#include <cstdint>
#include <cstddef>

#define BQ      8192
#define IN_DIM  1024
#define H_DIM   2048
#define OUT_DIM 1024

#if defined(__CUDA_ARCH_FEAT_SM103_ALL) || defined(__CUDA_ARCH_FEAT_SM100_ALL)
#define TC_OK 1
#else
#define TC_OK 0
#endif

// ---------------- scratch ----------------
__device__ float g_Crr [(size_t)OUT_DIM * H_DIM];   // RNA tf32 Cr
__device__ float g_Cir [(size_t)OUT_DIM * H_DIM];   // RNA tf32 Ci
__device__ float g_BrT [(size_t)IN_DIM * H_DIM];    // Br^T, RNA tf32
__device__ float g_BiTn[(size_t)IN_DIM * H_DIM];    // -Bi^T, RNA tf32
__device__ float g_E   [(size_t)OUT_DIM * IN_DIM];  // Cr@Br - Ci@Bi, RNA tf32
__device__ float g_E1  [(size_t)OUT_DIM * IN_DIM];  // split-K partial (Ci@Bi half, raw fp32)
__device__ float g_D   [(size_t)OUT_DIM * H_DIM];   // wr.*Cr - wi.*Ci, RNA tf32
__device__ int   g_flag[64];                        // per-fold-tile partial-ready flags

// ---------------- helpers ----------------
__device__ __forceinline__ float rna_tf32(float x) {
    uint32_t r;
    asm("cvt.rna.tf32.f32 %0, %1;" : "=r"(r) : "f"(x));
    return __uint_as_float(r);
}
__device__ __forceinline__ uint32_t smem_u32(const void* p) {
    return (uint32_t)__cvta_generic_to_shared(p);
}
__device__ __forceinline__ void cp16(uint32_t dst, const void* src) {
    asm volatile("cp.async.cg.shared.global [%0], [%1], 16;" :: "r"(dst), "l"(src));
}
__device__ __forceinline__ void cp_commit() { asm volatile("cp.async.commit_group;"); }
template <int N> __device__ __forceinline__ void cp_wait() {
    asm volatile("cp.async.wait_group %0;" :: "n"(N));
}
__device__ __forceinline__ uint32_t swz(uint32_t off) {   // SW128
    return off ^ ((off >> 3) & 0x70);
}
__device__ __forceinline__ void mbar_init(uint32_t addr, uint32_t cnt) {
    asm volatile("mbarrier.init.shared.b64 [%0], %1;" :: "r"(addr), "r"(cnt) : "memory");
}
__device__ __forceinline__ void mbar_wait(uint32_t addr, uint32_t parity) {
    asm volatile(
        "{\n\t.reg .pred P;\n\t"
        "W%=:\n\t"
        "mbarrier.try_wait.parity.shared::cta.b64 P, [%0], %1, 0x989680;\n\t"
        "@!P bra W%=;\n\t"
        "}" :: "r"(addr), "r"(parity) : "memory");
}
__device__ __forceinline__ void cp_arrive(uint32_t addr) {
    asm volatile("cp.async.mbarrier.arrive.noinc.shared::cta.b64 [%0];" :: "r"(addr) : "memory");
}
__device__ __forceinline__ void cluster_sync() {
    asm volatile("barrier.cluster.arrive.aligned;" ::: "memory");
    asm volatile("barrier.cluster.wait.aligned;" ::: "memory");
}
__device__ __forceinline__ uint32_t ctarank() {
    uint32_t r;
    asm("mov.u32 %0, %%cluster_ctarank;" : "=r"(r));
    return r;
}
// mma.sync fallback helpers
__device__ __forceinline__ void ldm4(uint32_t& r0, uint32_t& r1, uint32_t& r2, uint32_t& r3, uint32_t a) {
    asm volatile("ldmatrix.sync.aligned.m8n8.x4.shared.b16 {%0,%1,%2,%3}, [%4];"
                 : "=r"(r0), "=r"(r1), "=r"(r2), "=r"(r3) : "r"(a));
}
__device__ __forceinline__ void mma8(float* c, const uint32_t* a, uint32_t b0, uint32_t b1) {
    asm volatile("mma.sync.aligned.m16n8k8.row.col.f32.tf32.tf32.f32 "
                 "{%0,%1,%2,%3}, {%4,%5,%6,%7}, {%8,%9}, {%0,%1,%2,%3};"
                 : "+f"(c[0]), "+f"(c[1]), "+f"(c[2]), "+f"(c[3])
                 : "r"(a[0]), "r"(a[1]), "r"(a[2]), "r"(a[3]), "r"(b0), "r"(b1));
}

#define SST 20
#define STAGE_FLOATS (2 * 128 * SST)

__device__ __forceinline__ void load_tile(float* s, const float* g, int ld) {
#pragma unroll
    for (int c = 0; c < 2; c++) {
        int idx = threadIdx.x + c * 256;
        int row = idx >> 2;
        int kc  = (idx & 3) << 2;
        cp16(smem_u32(s + row * SST + kc), g + (size_t)row * ld + kc);
    }
}
__device__ __forceinline__ void mma_tile(float c[2][8][4], const float* As, const float* Bs,
                                         int wm, int wn, int lane) {
#pragma unroll
    for (int ks = 0; ks < 2; ks++) {
        const int k0 = ks * 8;
        uint32_t af[2][4];
        const int ar = (lane & 7) + ((lane >> 3) & 1) * 8;
        const int ac = k0 + (lane >> 4) * 4;
#pragma unroll
        for (int mi = 0; mi < 2; mi++) {
            uint32_t addr = smem_u32(As + (wm * 32 + mi * 16 + ar) * SST + ac);
            ldm4(af[mi][0], af[mi][1], af[mi][2], af[mi][3], addr);
        }
        const int br = (lane & 7) + ((lane >> 4) ? 8 : 0);
        const int bc = k0 + ((lane >> 3) & 1) * 4;
#pragma unroll
        for (int p = 0; p < 4; p++) {
            uint32_t b0, b1, b2, b3;
            uint32_t addr = smem_u32(Bs + (wn * 64 + p * 16 + br) * SST + bc);
            ldm4(b0, b1, b2, b3, addr);
#pragma unroll
            for (int mi = 0; mi < 2; mi++) {
                mma8(c[mi][2 * p],     af[mi], b0, b1);
                mma8(c[mi][2 * p + 1], af[mi], b2, b3);
            }
        }
    }
}

#if TC_OK
__device__ __forceinline__ void tc_commit(uint32_t mbar) {
    asm volatile("tcgen05.commit.cta_group::1.mbarrier::arrive::one.shared::cluster.b64 [%0];"
                 :: "r"(mbar) : "memory");
}
__device__ __forceinline__ void tc_commit_mc2(uint32_t mbar) {
    asm volatile(
        "tcgen05.commit.cta_group::2.mbarrier::arrive::one.shared::cluster.multicast::cluster.b64 [%0], %1;"
        :: "r"(mbar), "h"((uint16_t)3) : "memory");
}
__device__ __forceinline__ void mma_tf32_ss(uint32_t d_tmem, uint64_t a_desc, uint64_t b_desc,
                                            uint32_t idesc, bool enable) {
    uint32_t en = enable ? 1u : 0u;
    asm volatile(
        "{\n\t.reg .pred p;\n\t"
        "setp.ne.u32 p, %4, 0;\n\t"
        "tcgen05.mma.cta_group::1.kind::tf32 [%0], %1, %2, %3, {%5,%5,%5,%5}, p;\n\t}"
        :: "r"(d_tmem), "l"(a_desc), "l"(b_desc), "r"(idesc), "r"(en), "r"(0u) : "memory");
}
__device__ __forceinline__ void mma_tf32_ss2(uint32_t d_tmem, uint64_t a_desc, uint64_t b_desc,
                                             uint32_t idesc, bool enable) {
    uint32_t en = enable ? 1u : 0u;
    asm volatile(
        "{\n\t.reg .pred p;\n\t"
        "setp.ne.u32 p, %4, 0;\n\t"
        "tcgen05.mma.cta_group::2.kind::tf32 [%0], %1, %2, %3, {%5,%5,%5,%5,%5,%5,%5,%5}, p;\n\t}"
        :: "r"(d_tmem), "l"(a_desc), "l"(b_desc), "r"(idesc), "r"(en), "r"(0u) : "memory");
}
__device__ __forceinline__ uint64_t mk_desc(uint32_t addr) {
    return ((uint64_t)2 << 61) | ((uint64_t)1 << 46) | ((uint64_t)64 << 32) |
           ((uint64_t)1 << 16) | (((uint64_t)addr >> 4) & 0x3FFF);
}
__device__ __forceinline__ void ldtm32(uint32_t* r, uint32_t addr) {
    asm volatile(
        "tcgen05.ld.sync.aligned.32x32b.x32.b32 "
        "{%0,%1,%2,%3,%4,%5,%6,%7,%8,%9,%10,%11,%12,%13,%14,%15,"
        "%16,%17,%18,%19,%20,%21,%22,%23,%24,%25,%26,%27,%28,%29,%30,%31}, [%32];"
        : "=r"(r[0]), "=r"(r[1]), "=r"(r[2]), "=r"(r[3]),
          "=r"(r[4]), "=r"(r[5]), "=r"(r[6]), "=r"(r[7]),
          "=r"(r[8]), "=r"(r[9]), "=r"(r[10]), "=r"(r[11]),
          "=r"(r[12]), "=r"(r[13]), "=r"(r[14]), "=r"(r[15]),
          "=r"(r[16]), "=r"(r[17]), "=r"(r[18]), "=r"(r[19]),
          "=r"(r[20]), "=r"(r[21]), "=r"(r[22]), "=r"(r[23]),
          "=r"(r[24]), "=r"(r[25]), "=r"(r[26]), "=r"(r[27]),
          "=r"(r[28]), "=r"(r[29]), "=r"(r[30]), "=r"(r[31])
        : "r"(addr));
    asm volatile("tcgen05.wait::ld.sync.aligned;" ::: "memory");
}
#endif

// ---------------- merged prep ----------------
// grid 6144 x 256:
//   [0,2048)    BrT  (transpose + RNA); block 0 also zeroes fold flags
//   [2048,4096) BiTn (transpose + negate + RNA)
//   [4096,6144) fused: round Cr,Ci -> Crr,Cir AND D (fast intrinsics)
__global__ void prep_all(const float* __restrict__ Br, const float* __restrict__ Bi,
                         const float4* __restrict__ Cr4, const float4* __restrict__ Ci4,
                         const float* __restrict__ v_log, const float* __restrict__ theta_log) {
    const int b = blockIdx.x;
    if (b == 0 && threadIdx.x < 64) g_flag[threadIdx.x] = 0;
    if (b < 4096) {
        __shared__ float tile[32][33];
        const float* src = (b < 2048) ? Br : Bi;
        float* dst = (b < 2048) ? g_BrT : g_BiTn;
        const float sign = (b < 2048) ? 1.0f : -1.0f;
        const int lb = b & 2047;
        const int bx = lb & 31;
        const int by = lb >> 5;
        const int tx = threadIdx.x & 31, ty = threadIdx.x >> 5;
        const int cx = bx * 32 + tx;
        const int ry = by * 32 + ty;
#pragma unroll
        for (int j = 0; j < 32; j += 8)
            tile[ty + j][tx] = src[(size_t)(ry + j) * IN_DIM + cx];
        __syncthreads();
        const int ox = by * 32 + tx;
        const int oy = bx * 32 + ty;
#pragma unroll
        for (int j = 0; j < 32; j += 8)
            dst[(size_t)(oy + j) * H_DIM + ox] = rna_tf32(sign * tile[tx][ty + j]);
    } else {
        int i = (b - 4096) * 256 + threadIdx.x;
        int h0 = (i & (H_DIM / 4 - 1)) * 4;
        float4 cr = Cr4[i], ci = Ci4[i];
        float4 rr, ri;
        rr.x = rna_tf32(cr.x); rr.y = rna_tf32(cr.y);
        rr.z = rna_tf32(cr.z); rr.w = rna_tf32(cr.w);
        ri.x = rna_tf32(ci.x); ri.y = rna_tf32(ci.y);
        ri.z = rna_tf32(ci.z); ri.w = rna_tf32(ci.w);
        ((float4*)g_Crr)[i] = rr;
        ((float4*)g_Cir)[i] = ri;
        const float* c4r = (const float*)&cr;
        const float* c4i = (const float*)&ci;
        float o[4];
#pragma unroll
        for (int k = 0; k < 4; k++) {
            float mag = __expf(-__expf(v_log[h0 + k]));
            float ang = __expf(theta_log[h0 + k]);
            float sn, cs;
            __sincosf(ang, &sn, &cs);
            o[k] = rna_tf32(mag * cs * c4r[k] - mag * sn * c4i[k]);
        }
        ((float4*)g_D)[i] = make_float4(o[0], o[1], o[2], o[3]);
    }
}

// ---------------- split-K fold GEMM ----------------
// grid (8, 8, 2): z=0 computes Crr@BrT^T half (owns final E), z=1 computes Cir@BiTn^T half.
// z=1 stores raw partial to g_E1 + flags; z=0 adds partner partial, RNA-rounds, stores E.
__global__ void __launch_bounds__(256, 1) fold_k() {
    extern __shared__ __align__(16) char dsm[];
    const int tid = threadIdx.x;
    const int m0 = blockIdx.x * 128;
    const int n0 = blockIdx.y * 128;
    const int z  = blockIdx.z;
    const int tile = blockIdx.x * 8 + blockIdx.y;
    const float* A = (z ? g_Cir  : g_Crr) + (size_t)m0 * H_DIM;
    const float* B = (z ? g_BiTn : g_BrT) + (size_t)n0 * H_DIM;
    constexpr int NKT = 64;   // 2048 / 32

#if TC_OK
    constexpr int NS = 4;
    constexpr int TILE16K = 16384;
    constexpr int STAGE = 2 * TILE16K;
    const uint32_t sbase = (smem_u32(dsm) + 1023u) & ~1023u;

    __shared__ __align__(8) uint64_t mbar[2 * NS + 1];
    __shared__ uint32_t tmem_slot[1];

    const uint32_t fullA  = smem_u32(&mbar[0]);
    const uint32_t emptyA = smem_u32(&mbar[NS]);
    const uint32_t doneA  = smem_u32(&mbar[2 * NS]);

    if (tid < 32) {
        asm volatile("tcgen05.alloc.cta_group::1.sync.aligned.shared::cta.b32 [%0], %1;"
                     :: "r"(smem_u32(tmem_slot)), "r"(128u) : "memory");
    }
    if (tid == 0) {
#pragma unroll
        for (int s = 0; s < NS; s++) {
            mbar_init(fullA  + 8 * s, 128);
            mbar_init(emptyA + 8 * s, 1);
        }
        mbar_init(doneA, 1);
    }
    __syncthreads();
    const uint32_t tmem = tmem_slot[0];

    if (tid < 128) {
        for (int u = 0; u < NKT; u++) {
            const int s = u & (NS - 1);
            if (u >= NS) mbar_wait(emptyA + 8 * s, ((u / NS) - 1) & 1);
            const int k0 = u * 32;
            const uint32_t sa = sbase + s * STAGE;
            const uint32_t sb = sa + TILE16K;
#pragma unroll
            for (int c = 0; c < 8; c++) {
                int i = tid + c * 128;
                int row = i >> 3, kc = i & 7;
                cp16(sa + swz(row * 128 + kc * 16), A + (size_t)row * H_DIM + k0 + kc * 4);
            }
#pragma unroll
            for (int c = 0; c < 8; c++) {
                int i = tid + c * 128;
                int row = i >> 3, kc = i & 7;
                cp16(sb + swz(row * 128 + kc * 16), B + (size_t)row * H_DIM + k0 + kc * 4);
            }
            cp_arrive(fullA + 8 * s);
        }
    } else if (tid == 128) {
        asm volatile("tcgen05.fence::after_thread_sync;" ::: "memory");
        const uint32_t idesc = (1u << 4) | (2u << 7) | (2u << 10) |
                               ((128u / 8) << 17) | (8u << 24);
        for (int t = 0; t < NKT; t++) {
            const int s = t & (NS - 1);
            mbar_wait(fullA + 8 * s, (t / NS) & 1);
            asm volatile("fence.proxy.async.shared::cta;" ::: "memory");
            const uint64_t ad = mk_desc(sbase + s * STAGE);
            const uint64_t bd = mk_desc(sbase + s * STAGE + TILE16K);
#pragma unroll
            for (int k = 0; k < 4; k++)
                mma_tf32_ss(tmem, ad + 2 * k, bd + 2 * k, idesc, !(t == 0 && k == 0));
            tc_commit(emptyA + 8 * s);
        }
        tc_commit(doneA);
    }

    mbar_wait(doneA, 0);
    asm volatile("tcgen05.fence::after_thread_sync;" ::: "memory");

    if (tid < 128) {
        if (z == 1) {
            float* prow = g_E1 + (size_t)(m0 + tid) * IN_DIM + n0;
#pragma unroll
            for (int base = 0; base < 128; base += 32) {
                uint32_t r[32];
                ldtm32(r, tmem + base);
#pragma unroll
                for (int q = 0; q < 8; q++) {
                    float4 v;
                    v.x = __uint_as_float(r[4 * q + 0]);
                    v.y = __uint_as_float(r[4 * q + 1]);
                    v.z = __uint_as_float(r[4 * q + 2]);
                    v.w = __uint_as_float(r[4 * q + 3]);
                    *(float4*)(prow + base + 4 * q) = v;
                }
            }
        } else {
            // wait for partner partial
            if (tid == 0) {
                while (atomicAdd(&g_flag[tile], 0) == 0) {}
            }
        }
    }
    if (z == 1) {
        __syncthreads();
        if (tid == 0) {
            __threadfence();
            atomicAdd(&g_flag[tile], 1);
        }
    } else {
        __syncthreads();      // all threads see flag observed by tid 0
        __threadfence();
        if (tid < 128) {
            const float* prow = g_E1 + (size_t)(m0 + tid) * IN_DIM + n0;
            float* orow = g_E + (size_t)(m0 + tid) * IN_DIM + n0;
#pragma unroll
            for (int base = 0; base < 128; base += 32) {
                uint32_t r[32];
                ldtm32(r, tmem + base);
#pragma unroll
                for (int q = 0; q < 8; q++) {
                    float4 p = *(const float4*)(prow + base + 4 * q);
                    float4 v;
                    v.x = rna_tf32(__uint_as_float(r[4 * q + 0]) + p.x);
                    v.y = rna_tf32(__uint_as_float(r[4 * q + 1]) + p.y);
                    v.z = rna_tf32(__uint_as_float(r[4 * q + 2]) + p.z);
                    v.w = rna_tf32(__uint_as_float(r[4 * q + 3]) + p.w);
                    *(float4*)(orow + base + 4 * q) = v;
                }
            }
        }
    }
    asm volatile("tcgen05.fence::before_thread_sync;" ::: "memory");
    __syncthreads();
    if (tid < 32) {
        asm volatile("tcgen05.dealloc.cta_group::1.sync.aligned.b32 %0, %1;"
                     :: "r"(tmem), "r"(128u));
    }
#else
    // ---------------- fallback: mma.sync split-K fold ----------------
    float* smf = (float*)dsm;
    const int wid = tid >> 5, lane = tid & 31;
    const int wm = wid >> 1, wn = wid & 1;
    const int NKT16 = NKT * 2;
    float c[2][8][4] = {};
#pragma unroll 1
    for (int s = 0; s < 2; s++) {
        load_tile(smf + s * STAGE_FLOATS, A + s * 16, H_DIM);
        load_tile(smf + s * STAGE_FLOATS + 128 * SST, B + s * 16, H_DIM);
        cp_commit();
    }
#pragma unroll 1
    for (int t = 0; t < NKT16; t++) {
        if (t + 2 < NKT16) cp_wait<1>(); else cp_wait<0>();
        __syncthreads();
        if (t + 2 < NKT16) {
            int k0 = (t + 2) * 16;
            float* sb = smf + ((t + 2) % 3) * STAGE_FLOATS;
            load_tile(sb, A + k0, H_DIM);
            load_tile(sb + 128 * SST, B + k0, H_DIM);
            cp_commit();
        }
        const float* st = smf + (t % 3) * STAGE_FLOATS;
        mma_tile(c, st, st + 128 * SST, wm, wn, lane);
    }
    __syncthreads();

    const int g = lane >> 2, tq = lane & 3;
    if (z == 1) {
#pragma unroll
        for (int mi = 0; mi < 2; mi++)
#pragma unroll
            for (int ni = 0; ni < 8; ni++) {
                int col = n0 + wn * 64 + ni * 8 + 2 * tq;
#pragma unroll
                for (int hf = 0; hf < 2; hf++) {
                    int row = m0 + wm * 32 + mi * 16 + hf * 8 + g;
                    float2 o;
                    o.x = c[mi][ni][hf * 2 + 0];
                    o.y = c[mi][ni][hf * 2 + 1];
                    *(float2*)(g_E1 + (size_t)row * IN_DIM + col) = o;
                }
            }
        __syncthreads();
        if (tid == 0) { __threadfence(); atomicAdd(&g_flag[tile], 1); }
    } else {
        if (tid == 0) { while (atomicAdd(&g_flag[tile], 0) == 0) {} }
        __syncthreads();
        __threadfence();
#pragma unroll
        for (int mi = 0; mi < 2; mi++)
#pragma unroll
            for (int ni = 0; ni < 8; ni++) {
                int col = n0 + wn * 64 + ni * 8 + 2 * tq;
#pragma unroll
                for (int hf = 0; hf < 2; hf++) {
                    int row = m0 + wm * 32 + mi * 16 + hf * 8 + g;
                    float2 p = *(const float2*)(g_E1 + (size_t)row * IN_DIM + col);
                    float2 o;
                    o.x = rna_tf32(c[mi][ni][hf * 2 + 0] + p.x);
                    o.y = rna_tf32(c[mi][ni][hf * 2 + 1] + p.y);
                    *(float2*)(g_E + (size_t)row * IN_DIM + col) = o;
                }
            }
    }
#endif
}

// ---------------- cg2 main GEMM: pair tile M=256 x N=512, K split at KSPLIT ----------------
template <int NKT, int KSPLIT, int LDA0, int LDA1, int LDB0, int LDB1>
__global__ void __launch_bounds__(256, 1) __cluster_dims__(2, 1, 1)
gemm_2cta(const float* __restrict__ A0, const float* __restrict__ A1,
          const float* __restrict__ B0, const float* __restrict__ B1,
          float* __restrict__ out, int ldOut)
{
    extern __shared__ __align__(16) char dsm[];
    const int tid = threadIdx.x;

#if TC_OK
    constexpr int NS = 4;
    constexpr int TILE16K = 16384;
    constexpr int STAGE = 3 * TILE16K;
    const uint32_t sbase = (smem_u32(dsm) + 1023u) & ~1023u;

    __shared__ __align__(8) uint64_t mbar[3 * NS + 1];
    __shared__ uint32_t tmem_slot[1];

    const uint32_t rank = ctarank();
    const int m0 = (blockIdx.x >> 1) * 256 + (int)rank * 128;
    const int n0 = blockIdx.y * 512;

    const uint32_t fullL  = smem_u32(&mbar[0]);
    const uint32_t full2  = smem_u32(&mbar[NS]);
    const uint32_t emptyA = smem_u32(&mbar[2 * NS]);
    const uint32_t doneA  = smem_u32(&mbar[3 * NS]);

    if (tid < 32) {
        asm volatile("tcgen05.alloc.cta_group::2.sync.aligned.shared::cta.b32 [%0], %1;"
                     :: "r"(smem_u32(tmem_slot)), "r"(512u) : "memory");
    }
    if (tid == 0) {
#pragma unroll
        for (int s = 0; s < NS; s++) {
            mbar_init(fullL  + 8 * s, 128);
            mbar_init(full2  + 8 * s, 2);
            mbar_init(emptyA + 8 * s, 1);
        }
        mbar_init(doneA, 1);
    }
    __syncthreads();
    const uint32_t tmem = tmem_slot[0];
    cluster_sync();

    if (tid < 128) {
        // ---------------- producers ----------------
        for (int u = 0; u < NKT; u++) {
            const int s = u & (NS - 1);
            if (u >= NS) mbar_wait(emptyA + 8 * s, ((u / NS) - 1) & 1);
            const int k0 = u * 32;
            const float* Asrc; int lda;
            const float* Bsel; int ldb; int koff;
            if (k0 < KSPLIT) { Asrc = A0 + (size_t)m0 * LDA0 + k0; lda = LDA0;
                               Bsel = B0; ldb = LDB0; koff = k0; }
            else             { Asrc = A1 + (size_t)m0 * LDA1 + (k0 - KSPLIT); lda = LDA1;
                               Bsel = B1; ldb = LDB1; koff = k0 - KSPLIT; }
            const uint32_t sa = sbase + s * STAGE;
#pragma unroll
            for (int c = 0; c < 8; c++) {
                int i = tid + c * 128;
                int row = i >> 3, kc = i & 7;
                cp16(sa + swz(row * 128 + kc * 16), Asrc + (size_t)row * lda + kc * 4);
            }
#pragma unroll
            for (int r = 0; r < 2; r++) {
                const float* Bg = Bsel + (size_t)(n0 + r * 256 + (int)rank * 128) * ldb + koff;
                const uint32_t sb = sa + TILE16K + r * TILE16K;
#pragma unroll
                for (int c = 0; c < 8; c++) {
                    int i = tid + c * 128;
                    int row = i >> 3, kc = i & 7;
                    cp16(sb + swz(row * 128 + kc * 16), Bg + (size_t)row * ldb + kc * 4);
                }
            }
            cp_arrive(fullL + 8 * s);
        }
    } else if (tid == 128) {
        // ---------------- forwarder: local ready -> leader's full2 ----------------
        for (int t = 0; t < NKT; t++) {
            const int s = t & (NS - 1);
            mbar_wait(fullL + 8 * s, (t / NS) & 1);
            asm volatile("fence.proxy.async;" ::: "memory");
            asm volatile(
                "{\n\t.reg .b32 ra;\n\t"
                "mapa.shared::cluster.u32 ra, %0, %1;\n\t"
                "mbarrier.arrive.shared::cluster.b64 _, [ra];\n\t}"
                :: "r"(full2 + 8 * s), "r"(0) : "memory");
        }
    } else if (tid == 160 && rank == 0) {
        // ---------------- MMA issuer (leader) ----------------
        asm volatile("tcgen05.fence::after_thread_sync;" ::: "memory");
        const uint32_t idesc = (1u << 4) | (2u << 7) | (2u << 10) |
                               ((256u / 8) << 17) | ((256u / 16) << 24);
        for (int t = 0; t < NKT; t++) {
            const int s = t & (NS - 1);
            mbar_wait(full2 + 8 * s, (t / NS) & 1);
            const uint64_t ad = mk_desc(sbase + s * STAGE);
#pragma unroll
            for (int r = 0; r < 2; r++) {
                const uint64_t bd = mk_desc(sbase + s * STAGE + TILE16K + r * TILE16K);
#pragma unroll
                for (int k = 0; k < 4; k++)
                    mma_tf32_ss2(tmem + r * 256, ad + 2 * k, bd + 2 * k, idesc,
                                 !(t == 0 && k == 0));
            }
            tc_commit_mc2(emptyA + 8 * s);
        }
        tc_commit_mc2(doneA);
    }

    // ---------------- epilogue ----------------
    mbar_wait(doneA, 0);
    asm volatile("tcgen05.fence::after_thread_sync;" ::: "memory");

    if (tid < 128) {
        float* orow = out + (size_t)(m0 + tid) * ldOut + n0;
#pragma unroll
        for (int base = 0; base < 512; base += 32) {
            uint32_t r[32];
            ldtm32(r, tmem + base);
#pragma unroll
            for (int q = 0; q < 8; q++) {
                float4 v;
                v.x = __uint_as_float(r[4 * q + 0]);
                v.y = __uint_as_float(r[4 * q + 1]);
                v.z = __uint_as_float(r[4 * q + 2]);
                v.w = __uint_as_float(r[4 * q + 3]);
                *(float4*)(orow + base + 4 * q) = v;
            }
        }
    }
    asm volatile("tcgen05.fence::before_thread_sync;" ::: "memory");
    __syncthreads();
    cluster_sync();
    if (tid < 32) {
        asm volatile("tcgen05.relinquish_alloc_permit.cta_group::2.sync.aligned;");
        asm volatile("tcgen05.dealloc.cta_group::2.sync.aligned.b32 %0, %1;"
                     :: "r"(tmem), "r"(512u));
    }
    cluster_sync();
#else
    // ---------------- fallback: mma.sync ----------------
    float* smf = (float*)dsm;
    const int m0 = blockIdx.x * 128;
    const int n0 = blockIdx.y * 512;
    const int wid = tid >> 5, lane = tid & 31;
    const int wm = wid >> 1, wn = wid & 1;
    const int NKT16 = NKT * 2;

    for (int nh = 0; nh < 4; nh++) {
        const int n0h = n0 + nh * 128;
        float c[2][8][4] = {};
#pragma unroll 1
        for (int s = 0; s < 2; s++) {
            int k0 = s * 16;
            const float* Ag = (k0 < KSPLIT) ? A0 + (size_t)m0 * LDA0 + k0
                                            : A1 + (size_t)m0 * LDA1 + (k0 - KSPLIT);
            int lda = (k0 < KSPLIT) ? LDA0 : LDA1;
            const float* Bg = (k0 < KSPLIT) ? B0 + (size_t)n0h * LDB0 + k0
                                            : B1 + (size_t)n0h * LDB1 + (k0 - KSPLIT);
            int ldb = (k0 < KSPLIT) ? LDB0 : LDB1;
            load_tile(smf + s * STAGE_FLOATS, Ag, lda);
            load_tile(smf + s * STAGE_FLOATS + 128 * SST, Bg, ldb);
            cp_commit();
        }
#pragma unroll 1
        for (int t = 0; t < NKT16; t++) {
            if (t + 2 < NKT16) cp_wait<1>(); else cp_wait<0>();
            __syncthreads();
            if (t + 2 < NKT16) {
                int k0 = (t + 2) * 16;
                float* sb = smf + ((t + 2) % 3) * STAGE_FLOATS;
                const float* Ag = (k0 < KSPLIT) ? A0 + (size_t)m0 * LDA0 + k0
                                                : A1 + (size_t)m0 * LDA1 + (k0 - KSPLIT);
                int lda = (k0 < KSPLIT) ? LDA0 : LDA1;
                const float* Bg = (k0 < KSPLIT) ? B0 + (size_t)n0h * LDB0 + k0
                                                : B1 + (size_t)n0h * LDB1 + (k0 - KSPLIT);
                int ldb = (k0 < KSPLIT) ? LDB0 : LDB1;
                load_tile(sb, Ag, lda);
                load_tile(sb + 128 * SST, Bg, ldb);
                cp_commit();
            }
            const float* st = smf + (t % 3) * STAGE_FLOATS;
            mma_tile(c, st, st + 128 * SST, wm, wn, lane);
        }
        __syncthreads();

        const int g = lane >> 2, tq = lane & 3;
#pragma unroll
        for (int mi = 0; mi < 2; mi++)
#pragma unroll
            for (int ni = 0; ni < 8; ni++) {
                int col = n0h + wn * 64 + ni * 8 + 2 * tq;
#pragma unroll
                for (int hf = 0; hf < 2; hf++) {
                    int row = m0 + wm * 32 + mi * 16 + hf * 8 + g;
                    float2 o;
                    o.x = c[mi][ni][hf * 2 + 0];
                    o.y = c[mi][ni][hf * 2 + 1];
                    *(float2*)(out + (size_t)row * ldOut + col) = o;
                }
            }
    }
#endif
}

// ---------------- launch ----------------
extern "C" void kernel_launch(void* const* d_in, const int* in_sizes, int n_in,
                              void* d_out, int out_size) {
    const float* x         = (const float*)d_in[0];
    const float* h_prev    = (const float*)d_in[1];
    const float* Br        = (const float*)d_in[2];
    const float* Bi        = (const float*)d_in[3];
    const float* Cr        = (const float*)d_in[4];
    const float* Ci        = (const float*)d_in[5];
    const float* v_log     = (const float*)d_in[6];
    const float* theta_log = (const float*)d_in[7];

    float *p_E, *p_D;
    cudaGetSymbolAddress((void**)&p_E, g_E);
    cudaGetSymbolAddress((void**)&p_D, g_D);

    // main: out = [hp|x] @ [D|E]^T  (M=8192, N=1024, K=3072)
    auto* mainK = gemm_2cta<96, 2048, 2048, 1024, 2048, 1024>;

    const int smem_fold = 4 * (2 * 16384) + 1024;   // 132 KB
    const int smem_main = 4 * (3 * 16384) + 1024;   // 197632 B
    cudaFuncSetAttribute(fold_k, cudaFuncAttributeMaxDynamicSharedMemorySize, smem_fold);
    cudaFuncSetAttribute(mainK, cudaFuncAttributeMaxDynamicSharedMemorySize, smem_main);

    // launch 0: merged prep (transposes + Crr/Cir/D + flag reset)
    prep_all<<<6144, 256>>>(Br, Bi, (const float4*)Cr, (const float4*)Ci, v_log, theta_log);

    // launch 1: split-K fold — grid (8,8,2), 128 CTAs, one wave
    fold_k<<<dim3(8, 8, 2), 256, smem_fold>>>();

    // launch 2: main GEMM — grid (64, 2), cluster (2,1,1)
    mainK<<<dim3(2 * (BQ / 256), OUT_DIM / 512), 256, smem_main>>>(h_prev, x, p_D, p_E,
                                                                   (float*)d_out, OUT_DIM);
}